// round 11
// baseline (speedup 1.0000x reference)
#include <cuda_runtime.h>
#include <cuda_fp16.h>
#include <cstdint>

#define NN 10000
#define RR 100
#define EE 5000
#define NEDGE (RR * EE)

// ---------------- scratch (device globals; no allocations) ----------------
__device__ int   g_deg[RR * NN];
__device__ int   g_cnt[NN];
__device__ int   g_off[NN + 1];
__device__ int   g_cur[NN];
__device__ int   g_rec[NEDGE];            // packed (r<<16)|src, grouped by dst
__device__ float g_w[NEDGE];              // per-edge 1/deg, grouped by dst
__device__ unsigned int g_ctr;            // dynamic unit counter for gemm1
__device__ int   g_done[79];              // per-m-tile split-K completion counters
__device__ float g_x[NN * 128];           // x = x_drug @ drug_w (atomic accumulated)
__device__ __half g_xAh[NN * 128];        // x fp16-hi (written by gemm1 last finisher)
__device__ __half g_xAl[NN * 128];        // x fp16-lo
__device__ __half g_BtW_hi[128 * 2048];   // drug_w^T fp16-hi
__device__ __half g_BtW_lo[128 * 2048];   // drug_w^T fp16-lo
__device__ __half g_Bt1_hi[576 * 128];    // [basis1|root1]^T fp16-hi
__device__ __half g_Bt1_lo[576 * 128];
__device__ __half g_xb1h[NN * 512];       // x @ basis1 (fp16)
__device__ float g_root1[NN * 64];        // x @ root1 (fp32)
__device__ float g_h[NN * 64];            // layer-1 output (post relu)
__device__ float g_Bcat2[64 * 180];       // [basis2 (8x20) | root2 (20)]
__device__ __half g_xb2h[NN * 160];
__device__ float g_root2o[NN * 20];

// ---------------- helpers ----------------
__device__ __forceinline__ uint32_t smem_to_u32(const void* p) {
    uint32_t a;
    asm("{ .reg .u64 t; cvta.to.shared.u64 t, %1; cvt.u32.u64 %0, t; }" : "=r"(a) : "l"(p));
    return a;
}
#define CP_ASYNC16(dst_u32, gptr) \
    asm volatile("cp.async.cg.shared.global [%0], [%1], 16;" :: "r"(dst_u32), "l"(gptr) : "memory")
#define CP_COMMIT() asm volatile("cp.async.commit_group;" ::: "memory")
#define CP_WAIT1()  asm volatile("cp.async.wait_group 1;" ::: "memory")
#define CP_WAIT0()  asm volatile("cp.async.wait_group 0;" ::: "memory")

__device__ __forceinline__ void ldsm4(uint32_t* r, uint32_t addr) {
    asm volatile("ldmatrix.sync.aligned.m8n8.x4.shared.b16 {%0,%1,%2,%3}, [%4];"
        : "=r"(r[0]), "=r"(r[1]), "=r"(r[2]), "=r"(r[3]) : "r"(addr));
}
__device__ __forceinline__ void splitpair(float a, float b, uint32_t& h, uint32_t& l) {
    __half ha = __float2half_rn(a), hb = __float2half_rn(b);
    __half la = __float2half_rn(a - __half2float(ha));
    __half lb = __float2half_rn(b - __half2float(hb));
    __half2 H = __halves2half2(ha, hb), L = __halves2half2(la, lb);
    h = *(uint32_t*)&H;
    l = *(uint32_t*)&L;
}
__device__ __forceinline__ void mma16(float* d, const uint32_t* a, uint32_t b0, uint32_t b1) {
    asm volatile("mma.sync.aligned.m16n8k16.row.col.f32.f16.f16.f32 "
        "{%0,%1,%2,%3}, {%4,%5,%6,%7}, {%8,%9}, {%0,%1,%2,%3};"
        : "+f"(d[0]), "+f"(d[1]), "+f"(d[2]), "+f"(d[3])
        : "r"(a[0]), "r"(a[1]), "r"(a[2]), "r"(a[3]), "r"(b0), "r"(b1));
}

// ---------------- fused setup: zero + all weight prep ----------------
__global__ void setup_all(const float* __restrict__ w,
                          const float* __restrict__ basis1, const float* __restrict__ root1,
                          const float* __restrict__ basis2, const float* __restrict__ root2) {
    int stride = gridDim.x * blockDim.x;
    int i0 = blockIdx.x * blockDim.x + threadIdx.x;
    for (int i = i0; i < RR * NN; i += stride) g_deg[i] = 0;
    for (int i = i0; i < NN; i += stride) g_cnt[i] = 0;
    for (int i = i0; i < NN * 128; i += stride) g_x[i] = 0.0f;
    if (i0 == 0) g_ctr = 0u;
    if (i0 < 79) g_done[i0] = 0;
    for (int idx = i0; idx < 2048 * 128; idx += stride) {
        int k = idx >> 7, n = idx & 127;
        float v = w[idx];
        __half h = __float2half_rn(v);
        g_BtW_hi[n * 2048 + k] = h;
        g_BtW_lo[n * 2048 + k] = __float2half_rn(v - __half2float(h));
    }
    for (int idx = i0; idx < 576 * 128; idx += stride) {
        int c = idx >> 7, i = idx & 127;
        float v = (c < 512) ? basis1[(c >> 6) * 128 * 64 + i * 64 + (c & 63)]
                            : root1[i * 64 + (c - 512)];
        __half h = __float2half_rn(v);
        g_Bt1_hi[c * 128 + i] = h;
        g_Bt1_lo[c * 128 + i] = __float2half_rn(v - __half2float(h));
    }
    for (int idx = i0; idx < 64 * 180; idx += stride) {
        int i = idx / 180;
        int c = idx - i * 180;
        g_Bcat2[idx] = (c < 160) ? basis2[(c / 20) * 64 * 20 + i * 20 + (c % 20)]
                                 : root2[i * 20 + (c - 160)];
    }
}

// ---------------- degree + per-dst count ----------------
__global__ void deg_kernel(const int* __restrict__ ei) {
    int idx = blockIdx.x * blockDim.x + threadIdx.x;
    if (idx >= NEDGE) return;
    int r = idx / EE;
    int e = idx - r * EE;
    int dst = ei[r * 2 * EE + EE + e];
    atomicAdd(&g_deg[r * NN + dst], 1);
    atomicAdd(&g_cnt[dst], 1);
}

// ---------------- single-block exclusive scan ----------------
__global__ void scan_kernel() {
    __shared__ int sp[1024];
    int t = threadIdx.x;
    int base = t * 10;
    int loc[10];
    int s = 0;
#pragma unroll
    for (int j = 0; j < 10; j++) {
        int idx = base + j;
        int v = (idx < NN) ? g_cnt[idx] : 0;
        loc[j] = s;
        s += v;
    }
    sp[t] = s;
    __syncthreads();
    for (int off = 1; off < 1024; off <<= 1) {
        int v = (t >= off) ? sp[t - off] : 0;
        __syncthreads();
        sp[t] += v;
        __syncthreads();
    }
    int pre = (t > 0) ? sp[t - 1] : 0;
#pragma unroll
    for (int j = 0; j < 10; j++) {
        int idx = base + j;
        if (idx < NN) {
            int o = pre + loc[j];
            g_off[idx] = o;
            g_cur[idx] = o;
        }
    }
    if (t == 0) g_off[NN] = NEDGE;
}

// ---------------- scatter edges into dst buckets (+ per-edge 1/deg) ----------------
__global__ void scatter_kernel(const int* __restrict__ ei) {
    int idx = blockIdx.x * blockDim.x + threadIdx.x;
    if (idx >= NEDGE) return;
    int r = idx / EE;
    int e = idx - r * EE;
    const int* eir = ei + r * 2 * EE;
    int src = eir[e];
    int dst = eir[EE + e];
    int pos = atomicAdd(&g_cur[dst], 1);
    g_rec[pos] = (r << 16) | src;
    g_w[pos] = 1.0f / (float)max(g_deg[r * NN + dst], 1);
}

// ================= pipelined mma.sync fp16-split GEMM (3-product, ldmatrix) =================
#define LP2 20
#define STAGE_W (2 * 128 * LP2)

template<int DYN, int EPI, int AH>
__global__ void __launch_bounds__(256, 2)
mma_gemm(const float* __restrict__ Af,
         const __half* __restrict__ Ahg, const __half* __restrict__ Alg, int lda,
         const __half* __restrict__ Bth, const __half* __restrict__ Btl, int ldb,
         int Ntot, int nchunks,
         float* __restrict__ Cf, __half* __restrict__ Ch, float* __restrict__ Cr) {
    extern __shared__ uint32_t sm[];
    const uint32_t sbase = smem_to_u32(sm);
    __shared__ int s_u;
    __shared__ int s_last;

    const int tid = threadIdx.x;
    const int wid = tid >> 5;
    const int lane = tid & 31;
    const int g = lane >> 2;
    const int tig = lane & 3;
    const int m_warp = (wid & 3) * 32;
    const int n_warp = (wid >> 2) * 64;
    const int lrow = tid >> 1;        // 0..127
    const int part = tid & 1;         // 8-element half-row

    // ---- per-lane ldmatrix base offsets ----
    const int lrow8 = lane & 7;
    const int aRow = m_warp + ((lane >> 3) & 1) * 8 + lrow8;       // + mi*16
    const int aK = (lane >> 4) * 4;
    const uint32_t aOff0 = (uint32_t)((aRow)      * LP2 + aK) * 4; // mi=0 (bytes)
    const uint32_t aOff1 = (uint32_t)((aRow + 16) * LP2 + aK) * 4; // mi=1
    const int bCol = n_warp + (lane >> 4) * 8 + lrow8;             // + p*16
    const int bK = ((lane >> 3) & 1) * 4;
    const uint32_t bOffBase = (uint32_t)((128 + bCol) * LP2 + bK) * 4;

    float4 rAv[2][2];                 // A register prefetch slots (AH=0)

    while (true) {
        int m0, n0, kbeg0;
        if (DYN) {
            __syncthreads();                 // prior unit's compute done; smem reusable
            if (tid == 0) s_u = (int)atomicAdd(&g_ctr, 1u);
            __syncthreads();
            int u = s_u;
            if (u >= 79 * 8) return;
            m0 = (u % 79) * 128;
            n0 = 0;
            kbeg0 = (u / 79) * 256;
        } else {
            m0 = blockIdx.y * 128;
            n0 = blockIdx.x * 128;
            kbeg0 = 0;
        }

        const int nch = nchunks;
        const int gm = m0 + lrow;
        const int gn = n0 + lrow;
        const bool mok = (gm < NN);
        const bool nok = (gn < Ntot);

        // ---- issue helpers ----
        auto issueA = [&](int ch, int slot, int st) {
            int kbeg = kbeg0 + ch * 16;
            if (AH == 0) {
                if (mok) {
                    const float* ap = Af + (size_t)gm * lda + kbeg + part * 8;
                    rAv[slot][0] = *(const float4*)ap;
                    rAv[slot][1] = *(const float4*)(ap + 4);
                } else {
                    rAv[slot][0] = make_float4(0.f, 0.f, 0.f, 0.f);
                    rAv[slot][1] = make_float4(0.f, 0.f, 0.f, 0.f);
                }
            } else {
                if (mok) {
                    uint32_t d = sbase + (uint32_t)(st * STAGE_W + lrow * LP2 + part * 4) * 4;
                    CP_ASYNC16(d,      Ahg + (size_t)gm * lda + kbeg + part * 8);
                    CP_ASYNC16(d + 32, Alg + (size_t)gm * lda + kbeg + part * 8);
                }
            }
        };
        auto stsA = [&](int slot, int st) {   // AH=0 only
            uint4 H, L;
            splitpair(rAv[slot][0].x, rAv[slot][0].y, H.x, L.x);
            splitpair(rAv[slot][0].z, rAv[slot][0].w, H.y, L.y);
            splitpair(rAv[slot][1].x, rAv[slot][1].y, H.z, L.z);
            splitpair(rAv[slot][1].z, rAv[slot][1].w, H.w, L.w);
            uint32_t* p = sm + st * STAGE_W + lrow * LP2 + part * 4;
            *(uint4*)p = H;
            *(uint4*)(p + 8) = L;
        };
        auto issueB = [&](int ch, int st) {
            if (nok) {
                int kbeg = kbeg0 + ch * 16;
                uint32_t d = sbase + (uint32_t)(st * STAGE_W + 128 * LP2 + lrow * LP2 + part * 4) * 4;
                CP_ASYNC16(d,      Bth + (size_t)gn * ldb + kbeg + part * 8);
                CP_ASYNC16(d + 32, Btl + (size_t)gn * ldb + kbeg + part * 8);
            }
        };

        float acc[2][8][4];
#pragma unroll
        for (int i = 0; i < 2; i++)
#pragma unroll
            for (int j = 0; j < 8; j++)
#pragma unroll
                for (int q = 0; q < 4; q++) acc[i][j][q] = 0.f;

        // ---- prologue: chunks 0 and 1 in flight ----
        issueA(0, 0, 0); issueB(0, 0); CP_COMMIT();
        issueA(1, 1, 1); issueB(1, 1); CP_COMMIT();
        if (AH == 0) stsA(0, 0);

        // ---- main pipeline ----
        for (int ch = 0; ch < nch; ch++) {
            if (ch + 1 < nch) { CP_WAIT1(); } else { CP_WAIT0(); }
            __syncthreads();

            if (AH == 0 && ch + 1 < nch) stsA((ch + 1) & 1, (ch + 1) % 3);
            if (ch + 2 < nch) {
                issueA(ch + 2, ch & 1, (ch + 2) % 3);
                issueB(ch + 2, (ch + 2) % 3);
                CP_COMMIT();
            }

            // ---- compute chunk ch on stage ch%3 (ldmatrix fragments) ----
            const uint32_t stb = sbase + (uint32_t)((ch % 3) * STAGE_W) * 4;
            uint32_t ah[2][4], al[2][4];
            ldsm4(ah[0], stb + aOff0);
            ldsm4(ah[1], stb + aOff1);
            ldsm4(al[0], stb + aOff0 + 32);
            ldsm4(al[1], stb + aOff1 + 32);
#pragma unroll
            for (int p = 0; p < 4; p++) {
                uint32_t bAddr = stb + bOffBase + (uint32_t)(p * 16 * LP2) * 4;
                uint32_t bh[4], bl[4];
                ldsm4(bh, bAddr);
                ldsm4(bl, bAddr + 32);
                const int nj0 = 2 * p, nj1 = 2 * p + 1;
                mma16(acc[0][nj0], ah[0], bh[0], bh[1]);
                mma16(acc[1][nj0], ah[1], bh[0], bh[1]);
                mma16(acc[0][nj1], ah[0], bh[2], bh[3]);
                mma16(acc[1][nj1], ah[1], bh[2], bh[3]);
                mma16(acc[0][nj0], al[0], bh[0], bh[1]);
                mma16(acc[1][nj0], al[1], bh[0], bh[1]);
                mma16(acc[0][nj1], al[0], bh[2], bh[3]);
                mma16(acc[1][nj1], al[1], bh[2], bh[3]);
                mma16(acc[0][nj0], ah[0], bl[0], bl[1]);
                mma16(acc[1][nj0], ah[1], bl[0], bl[1]);
                mma16(acc[0][nj1], ah[0], bl[2], bl[3]);
                mma16(acc[1][nj1], ah[1], bl[2], bl[3]);
            }
        }

        // ---- epilogue ----
#pragma unroll
        for (int mi = 0; mi < 2; mi++) {
            int r0 = m0 + m_warp + mi * 16 + g;
            int r1 = r0 + 8;
#pragma unroll
            for (int nj = 0; nj < 8; nj++) {
                int gc = n0 + n_warp + nj * 8 + tig * 2;
                if (EPI == 0) {
                    if (r0 < NN) {
                        atomicAdd(&Cf[(size_t)r0 * 128 + gc],     acc[mi][nj][0]);
                        atomicAdd(&Cf[(size_t)r0 * 128 + gc + 1], acc[mi][nj][1]);
                    }
                    if (r1 < NN) {
                        atomicAdd(&Cf[(size_t)r1 * 128 + gc],     acc[mi][nj][2]);
                        atomicAdd(&Cf[(size_t)r1 * 128 + gc + 1], acc[mi][nj][3]);
                    }
                } else {
                    if (gc < 512) {
                        __half2 p0 = __floats2half2_rn(acc[mi][nj][0], acc[mi][nj][1]);
                        __half2 p1 = __floats2half2_rn(acc[mi][nj][2], acc[mi][nj][3]);
                        if (r0 < NN) *(__half2*)&Ch[(size_t)r0 * 512 + gc] = p0;
                        if (r1 < NN) *(__half2*)&Ch[(size_t)r1 * 512 + gc] = p1;
                    } else if (gc < 576) {
                        int rc = gc - 512;
                        if (r0 < NN) {
                            float2 f = make_float2(acc[mi][nj][0], acc[mi][nj][1]);
                            *(float2*)&Cr[(size_t)r0 * 64 + rc] = f;
                        }
                        if (r1 < NN) {
                            float2 f = make_float2(acc[mi][nj][2], acc[mi][nj][3]);
                            *(float2*)&Cr[(size_t)r1 * 64 + rc] = f;
                        }
                    }
                }
            }
        }

        // ---- GEMM1 only: last split-K finisher converts this m-tile to fp16 hi/lo ----
        if (EPI == 0) {
            __threadfence();
            __syncthreads();
            if (tid == 0) {
                int old = atomicAdd(&g_done[m0 >> 7], 1);
                s_last = (old == 7) ? 1 : 0;
            }
            __syncthreads();
            if (s_last) {
                __threadfence();
                for (int i = tid; i < 128 * 128; i += 256) {
                    int m = m0 + (i >> 7);
                    if (m < NN) {
                        int idx = m * 128 + (i & 127);
                        float v = Cf[idx];
                        __half h = __float2half_rn(v);
                        g_xAh[idx] = h;
                        g_xAl[idx] = __float2half_rn(v - __half2float(h));
                    }
                }
            }
        }
        if (!DYN) return;
    }
}

// ---------------- fp32 tiled GEMM for xb2 with fused fp16/fp32 split store ----------------
__global__ void __launch_bounds__(256)
sgemm_split(const float* __restrict__ A, const float* __restrict__ B, int M, int N, int K) {
    __shared__ float As[128][16];
    __shared__ float Bs[16][64];

    const int m0 = blockIdx.y * 128;
    const int n0 = blockIdx.x * 64;
    const int tid = threadIdx.x;
    const int tx = tid & 15;
    const int ty = tid >> 4;
    const int a_row = tid >> 1;
    const int a_col = (tid & 1) * 8;
    const int b_row = tid >> 4;
    const int b_col = (tid & 15) * 4;

    float acc[8][4];
#pragma unroll
    for (int i = 0; i < 8; i++)
#pragma unroll
        for (int j = 0; j < 4; j++) acc[i][j] = 0.0f;

    for (int k0 = 0; k0 < K; k0 += 16) {
        if (m0 + a_row < M) {
            const float* ap = A + (size_t)(m0 + a_row) * K + k0 + a_col;
            *(float4*)&As[a_row][a_col]     = *(const float4*)(ap);
            *(float4*)&As[a_row][a_col + 4] = *(const float4*)(ap + 4);
        } else {
            float4 z = make_float4(0.f, 0.f, 0.f, 0.f);
            *(float4*)&As[a_row][a_col]     = z;
            *(float4*)&As[a_row][a_col + 4] = z;
        }
        if (n0 + b_col + 3 < N) {
            *(float4*)&Bs[b_row][b_col] =
                *(const float4*)(B + (size_t)(k0 + b_row) * N + n0 + b_col);
        } else {
#pragma unroll
            for (int j = 0; j < 4; j++)
                Bs[b_row][b_col + j] =
                    (n0 + b_col + j < N) ? B[(size_t)(k0 + b_row) * N + n0 + b_col + j] : 0.0f;
        }
        __syncthreads();

#pragma unroll
        for (int kk = 0; kk < 16; kk++) {
            float rB[4];
            *(float4*)rB = *(const float4*)&Bs[kk][tx * 4];
#pragma unroll
            for (int i = 0; i < 8; i++) {
                float a = As[ty * 8 + i][kk];
                acc[i][0] += a * rB[0];
                acc[i][1] += a * rB[1];
                acc[i][2] += a * rB[2];
                acc[i][3] += a * rB[3];
            }
        }
        __syncthreads();
    }

#pragma unroll
    for (int i = 0; i < 8; i++) {
        int m = m0 + ty * 8 + i;
        if (m >= M) continue;
#pragma unroll
        for (int j = 0; j < 4; j++) {
            int n = n0 + tx * 4 + j;
            if (n >= N) continue;
            float v = acc[i][j];
            if (n < 160) g_xb2h[(size_t)m * 160 + n] = __float2half(v);
            else g_root2o[(size_t)m * 20 + (n - 160)] = v;
        }
    }
}

// ---------------- layer-1 aggregation (fp16 gathers, streamed 1/deg, fused epilogue) ------
__global__ void agg1_kernel(const float* __restrict__ comp, const float* __restrict__ bias) {
    int w = (blockIdx.x * blockDim.x + threadIdx.x) >> 5;
    int lane = threadIdx.x & 31;
    if (w >= NN) return;
    int beg = g_off[w];
    int end = g_off[w + 1];

    float ax = 0.f, ay = 0.f;
    int rec = (beg < end) ? g_rec[beg] : 0;
    float inv = (beg < end) ? g_w[beg] : 0.f;
    for (int i = beg; i < end; i++) {
        int src = rec & 0xFFFF;
        int r = rec >> 16;
        if (i + 1 < end) rec = g_rec[i + 1];
        float inv_next = (i + 1 < end) ? g_w[i + 1] : 0.f;
        float4 c0 = *(const float4*)(comp + r * 8);
        float4 c1 = *(const float4*)(comp + r * 8 + 4);
        const __half2* xr = (const __half2*)(g_xb1h + (size_t)src * 512);
        float mx = 0.f, my = 0.f;
        float2 f;
        f = __half22float2(xr[0 * 32 + lane]); mx += c0.x * f.x; my += c0.x * f.y;
        f = __half22float2(xr[1 * 32 + lane]); mx += c0.y * f.x; my += c0.y * f.y;
        f = __half22float2(xr[2 * 32 + lane]); mx += c0.z * f.x; my += c0.z * f.y;
        f = __half22float2(xr[3 * 32 + lane]); mx += c0.w * f.x; my += c0.w * f.y;
        f = __half22float2(xr[4 * 32 + lane]); mx += c1.x * f.x; my += c1.x * f.y;
        f = __half22float2(xr[5 * 32 + lane]); mx += c1.y * f.x; my += c1.y * f.y;
        f = __half22float2(xr[6 * 32 + lane]); mx += c1.z * f.x; my += c1.z * f.y;
        f = __half22float2(xr[7 * 32 + lane]); mx += c1.w * f.x; my += c1.w * f.y;
        ax += inv * mx;
        ay += inv * my;
        inv = inv_next;
    }
    int o = lane * 2;
    float r0 = ax + g_root1[w * 64 + o]     + bias[o];
    float r1 = ay + g_root1[w * 64 + o + 1] + bias[o + 1];
    g_h[w * 64 + o]     = fmaxf(r0, 0.f);
    g_h[w * 64 + o + 1] = fmaxf(r1, 0.f);
}

// ---------------- layer-2 aggregation (fp16 gathers, streamed 1/deg, fused epilogue) ------
__global__ void agg2_kernel(const float* __restrict__ comp, const float* __restrict__ bias,
                            float* __restrict__ out) {
    int w = (blockIdx.x * blockDim.x + threadIdx.x) >> 5;
    int lane = threadIdx.x & 31;
    if (w >= NN) return;
    int beg = g_off[w];
    int end = g_off[w + 1];
    int l = (lane < 20) ? lane : 0;

    float acc = 0.f;
    int rec = (beg < end) ? g_rec[beg] : 0;
    float inv = (beg < end) ? g_w[beg] : 0.f;
    for (int i = beg; i < end; i++) {
        int src = rec & 0xFFFF;
        int r = rec >> 16;
        if (i + 1 < end) rec = g_rec[i + 1];
        float inv_next = (i + 1 < end) ? g_w[i + 1] : 0.f;
        float4 c0 = *(const float4*)(comp + r * 8);
        float4 c1 = *(const float4*)(comp + r * 8 + 4);
        const __half* xr = g_xb2h + (size_t)src * 160;
        float m = 0.f;
        m += c0.x * __half2float(xr[0 * 20 + l]);
        m += c0.y * __half2float(xr[1 * 20 + l]);
        m += c0.z * __half2float(xr[2 * 20 + l]);
        m += c0.w * __half2float(xr[3 * 20 + l]);
        m += c1.x * __half2float(xr[4 * 20 + l]);
        m += c1.y * __half2float(xr[5 * 20 + l]);
        m += c1.z * __half2float(xr[6 * 20 + l]);
        m += c1.w * __half2float(xr[7 * 20 + l]);
        acc += inv * m;
        inv = inv_next;
    }
    if (lane < 20) {
        out[w * 20 + lane] = acc + g_root2o[w * 20 + lane] + bias[lane];
    }
}

// ---------------- launch ----------------
extern "C" void kernel_launch(void* const* d_in, const int* in_sizes, int n_in,
                              void* d_out, int out_size) {
    const float* x_drug = (const float*)d_in[0];
    const float* drug_w = (const float*)d_in[1];
    const int*   ei     = (const int*)d_in[2];
    const float* basis1 = (const float*)d_in[3];
    const float* comp1  = (const float*)d_in[4];
    const float* root1  = (const float*)d_in[5];
    const float* bias1  = (const float*)d_in[6];
    const float* basis2 = (const float*)d_in[7];
    const float* comp2  = (const float*)d_in[8];
    const float* root2  = (const float*)d_in[9];
    const float* bias2  = (const float*)d_in[10];
    float* out = (float*)d_out;

    void *px, *pxah, *pxal, *pbwh, *pbwl, *pb1h, *pb1l, *pxb1h, *proot1, *ph, *pb2;
    cudaGetSymbolAddress(&px,     g_x);
    cudaGetSymbolAddress(&pxah,   g_xAh);
    cudaGetSymbolAddress(&pxal,   g_xAl);
    cudaGetSymbolAddress(&pbwh,   g_BtW_hi);
    cudaGetSymbolAddress(&pbwl,   g_BtW_lo);
    cudaGetSymbolAddress(&pb1h,   g_Bt1_hi);
    cudaGetSymbolAddress(&pb1l,   g_Bt1_lo);
    cudaGetSymbolAddress(&pxb1h,  g_xb1h);
    cudaGetSymbolAddress(&proot1, g_root1);
    cudaGetSymbolAddress(&ph,     g_h);
    cudaGetSymbolAddress(&pb2,    g_Bcat2);

    const int SMEM = 3 * STAGE_W * 4;   // 61440 bytes
    cudaFuncSetAttribute(mma_gemm<1, 0, 0>, cudaFuncAttributeMaxDynamicSharedMemorySize, SMEM);
    cudaFuncSetAttribute(mma_gemm<0, 1, 1>, cudaFuncAttributeMaxDynamicSharedMemorySize, SMEM);

    // 0: fused setup (zero + weight prep)
    setup_all<<<1024, 256>>>(drug_w, basis1, root1, basis2, root2);
    // 1: degree counts (independent of GEMM chain)
    deg_kernel<<<(NEDGE + 255) / 256, 256>>>(ei);
    // 2: CSR offsets
    scan_kernel<<<1, 1024>>>();
    // 3: x = x_drug @ drug_w, fused last-finisher fp16 hi/lo convert (profiled launch)
    mma_gemm<1, 0, 0><<<296, 256, SMEM>>>(
        x_drug, nullptr, nullptr, 2048,
        (const __half*)pbwh, (const __half*)pbwl, 2048,
        128, 16, (float*)px, nullptr, nullptr);
    // 4: scatter edges (+ per-edge 1/deg)
    scatter_kernel<<<(NEDGE + 255) / 256, 256>>>(ei);
    // 5: xb1 = x @ [basis1|root1]
    mma_gemm<0, 1, 1><<<dim3(5, 79), 256, SMEM>>>(
        nullptr, (const __half*)pxah, (const __half*)pxal, 128,
        (const __half*)pb1h, (const __half*)pb1l, 128,
        576, 8, nullptr, (__half*)pxb1h, (float*)proot1);
    // 6: layer-1 aggregation + relu
    agg1_kernel<<<(NN * 32 + 255) / 256, 256>>>(comp1, bias1);
    // 7: xb2 = h @ [basis2|root2] with fused split store
    sgemm_split<<<dim3(3, 79), 256>>>((const float*)ph, (const float*)pb2, NN, 180, 64);
    // 8: layer-2 aggregation -> out
    agg2_kernel<<<(NN * 32 + 255) / 256, 256>>>(comp2, bias2, out);
}

// round 12
// speedup vs baseline: 1.0884x; 1.0884x over previous
#include <cuda_runtime.h>
#include <cuda_fp16.h>
#include <cstdint>

#define NN 10000
#define RR 100
#define EE 5000
#define NEDGE (RR * EE)

// ---------------- scratch (device globals; no allocations) ----------------
__device__ int   g_deg[RR * NN];
__device__ int   g_cnt[NN];
__device__ int   g_off[NN + 1];
__device__ int   g_cur[NN];
__device__ int2  g_recw[NEDGE];           // packed {(r<<16)|src, 1/deg bits}, grouped by dst
__device__ unsigned int g_ctr;            // dynamic unit counter for gemm1
__device__ float g_x[NN * 128];           // x = x_drug @ drug_w (atomic accumulated)
__device__ __half g_xAh[NN * 128];        // x fp16-hi (for xb1 gemm A)
__device__ __half g_xAl[NN * 128];        // x fp16-lo
__device__ __half g_BtW_hi[128 * 2048];   // drug_w^T fp16-hi
__device__ __half g_BtW_lo[128 * 2048];   // drug_w^T fp16-lo
__device__ __half g_Bt1_hi[576 * 128];    // [basis1|root1]^T fp16-hi
__device__ __half g_Bt1_lo[576 * 128];
__device__ __half g_xb1h[NN * 512];       // x @ basis1 (fp16)
__device__ float g_root1[NN * 64];        // x @ root1 (fp32)
__device__ float g_h[NN * 64];            // layer-1 output (post relu)
__device__ float g_Bcat2[64 * 180];       // [basis2 (8x20) | root2 (20)]
__device__ __half g_xb2h[NN * 160];
__device__ float g_root2o[NN * 20];

// ---------------- helpers ----------------
__device__ __forceinline__ uint32_t smem_to_u32(const void* p) {
    uint32_t a;
    asm("{ .reg .u64 t; cvta.to.shared.u64 t, %1; cvt.u32.u64 %0, t; }" : "=r"(a) : "l"(p));
    return a;
}
#define CP_ASYNC16(dst_u32, gptr) \
    asm volatile("cp.async.cg.shared.global [%0], [%1], 16;" :: "r"(dst_u32), "l"(gptr) : "memory")
#define CP_COMMIT() asm volatile("cp.async.commit_group;" ::: "memory")
#define CP_WAIT1()  asm volatile("cp.async.wait_group 1;" ::: "memory")
#define CP_WAIT0()  asm volatile("cp.async.wait_group 0;" ::: "memory")

__device__ __forceinline__ void ldsm4(uint32_t* r, uint32_t addr) {
    asm volatile("ldmatrix.sync.aligned.m8n8.x4.shared.b16 {%0,%1,%2,%3}, [%4];"
        : "=r"(r[0]), "=r"(r[1]), "=r"(r[2]), "=r"(r[3]) : "r"(addr));
}
__device__ __forceinline__ void splitpair(float a, float b, uint32_t& h, uint32_t& l) {
    __half ha = __float2half_rn(a), hb = __float2half_rn(b);
    __half la = __float2half_rn(a - __half2float(ha));
    __half lb = __float2half_rn(b - __half2float(hb));
    __half2 H = __halves2half2(ha, hb), L = __halves2half2(la, lb);
    h = *(uint32_t*)&H;
    l = *(uint32_t*)&L;
}
__device__ __forceinline__ void mma16(float* d, const uint32_t* a, uint32_t b0, uint32_t b1) {
    asm volatile("mma.sync.aligned.m16n8k16.row.col.f32.f16.f16.f32 "
        "{%0,%1,%2,%3}, {%4,%5,%6,%7}, {%8,%9}, {%0,%1,%2,%3};"
        : "+f"(d[0]), "+f"(d[1]), "+f"(d[2]), "+f"(d[3])
        : "r"(a[0]), "r"(a[1]), "r"(a[2]), "r"(a[3]), "r"(b0), "r"(b1));
}

// ---------------- fused setup: zero + all weight prep ----------------
__global__ void setup_all(const float* __restrict__ w,
                          const float* __restrict__ basis1, const float* __restrict__ root1,
                          const float* __restrict__ basis2, const float* __restrict__ root2) {
    int stride = gridDim.x * blockDim.x;
    int i0 = blockIdx.x * blockDim.x + threadIdx.x;
    for (int i = i0; i < RR * NN; i += stride) g_deg[i] = 0;
    for (int i = i0; i < NN; i += stride) g_cnt[i] = 0;
    for (int i = i0; i < NN * 128; i += stride) g_x[i] = 0.0f;
    if (i0 == 0) g_ctr = 0u;
    for (int idx = i0; idx < 2048 * 128; idx += stride) {
        int k = idx >> 7, n = idx & 127;
        float v = w[idx];
        __half h = __float2half_rn(v);
        g_BtW_hi[n * 2048 + k] = h;
        g_BtW_lo[n * 2048 + k] = __float2half_rn(v - __half2float(h));
    }
    for (int idx = i0; idx < 576 * 128; idx += stride) {
        int c = idx >> 7, i = idx & 127;
        float v = (c < 512) ? basis1[(c >> 6) * 128 * 64 + i * 64 + (c & 63)]
                            : root1[i * 64 + (c - 512)];
        __half h = __float2half_rn(v);
        g_Bt1_hi[c * 128 + i] = h;
        g_Bt1_lo[c * 128 + i] = __float2half_rn(v - __half2float(h));
    }
    for (int idx = i0; idx < 64 * 180; idx += stride) {
        int i = idx / 180;
        int c = idx - i * 180;
        g_Bcat2[idx] = (c < 160) ? basis2[(c / 20) * 64 * 20 + i * 20 + (c % 20)]
                                 : root2[i * 20 + (c - 160)];
    }
}

// ---------------- fused: g_x fp16 split + degree count ----------------
__global__ void cvtx_deg(const int* __restrict__ ei) {
    int stride = gridDim.x * blockDim.x;
    int i0 = blockIdx.x * blockDim.x + threadIdx.x;
    for (int idx = i0; idx < NN * 128; idx += stride) {
        float v = g_x[idx];
        __half h = __float2half_rn(v);
        g_xAh[idx] = h;
        g_xAl[idx] = __float2half_rn(v - __half2float(h));
    }
    for (int idx = i0; idx < NEDGE; idx += stride) {
        int r = idx / EE;
        int e = idx - r * EE;
        int dst = ei[r * 2 * EE + EE + e];
        atomicAdd(&g_deg[r * NN + dst], 1);
        atomicAdd(&g_cnt[dst], 1);
    }
}

// ---------------- single-block exclusive scan ----------------
__global__ void scan_kernel() {
    __shared__ int sp[1024];
    int t = threadIdx.x;
    int base = t * 10;
    int loc[10];
    int s = 0;
#pragma unroll
    for (int j = 0; j < 10; j++) {
        int idx = base + j;
        int v = (idx < NN) ? g_cnt[idx] : 0;
        loc[j] = s;
        s += v;
    }
    sp[t] = s;
    __syncthreads();
    for (int off = 1; off < 1024; off <<= 1) {
        int v = (t >= off) ? sp[t - off] : 0;
        __syncthreads();
        sp[t] += v;
        __syncthreads();
    }
    int pre = (t > 0) ? sp[t - 1] : 0;
#pragma unroll
    for (int j = 0; j < 10; j++) {
        int idx = base + j;
        if (idx < NN) {
            int o = pre + loc[j];
            g_off[idx] = o;
            g_cur[idx] = o;
        }
    }
    if (t == 0) g_off[NN] = NEDGE;
}

// ---------------- scatter edges into dst buckets (packed rec + 1/deg) ----------------
__global__ void scatter_kernel(const int* __restrict__ ei) {
    int idx = blockIdx.x * blockDim.x + threadIdx.x;
    if (idx >= NEDGE) return;
    int r = idx / EE;
    int e = idx - r * EE;
    const int* eir = ei + r * 2 * EE;
    int src = eir[e];
    int dst = eir[EE + e];
    int pos = atomicAdd(&g_cur[dst], 1);
    float w = 1.0f / (float)max(g_deg[r * NN + dst], 1);
    g_recw[pos] = make_int2((r << 16) | src, __float_as_int(w));
}

// ================= pipelined mma.sync fp16-split GEMM (3-product, ldmatrix) =================
#define LP2 20
#define STAGE_W (2 * 128 * LP2)

template<int DYN, int EPI, int AH>
__global__ void __launch_bounds__(256, 2)
mma_gemm(const float* __restrict__ Af,
         const __half* __restrict__ Ahg, const __half* __restrict__ Alg, int lda,
         const __half* __restrict__ Bth, const __half* __restrict__ Btl, int ldb,
         int Ntot, int nchunks,
         float* __restrict__ Cf, __half* __restrict__ Ch, float* __restrict__ Cr) {
    extern __shared__ uint32_t sm[];
    const uint32_t sbase = smem_to_u32(sm);
    __shared__ int s_u;

    const int tid = threadIdx.x;
    const int wid = tid >> 5;
    const int lane = tid & 31;
    const int g = lane >> 2;
    const int tig = lane & 3;
    const int m_warp = (wid & 3) * 32;
    const int n_warp = (wid >> 2) * 64;
    const int lrow = tid >> 1;        // 0..127
    const int part = tid & 1;         // 8-element half-row

    // ---- per-lane ldmatrix base offsets ----
    const int lrow8 = lane & 7;
    const int aRow = m_warp + ((lane >> 3) & 1) * 8 + lrow8;       // + mi*16
    const int aK = (lane >> 4) * 4;
    const uint32_t aOff0 = (uint32_t)((aRow)      * LP2 + aK) * 4; // mi=0 (bytes)
    const uint32_t aOff1 = (uint32_t)((aRow + 16) * LP2 + aK) * 4; // mi=1
    const int bCol = n_warp + (lane >> 4) * 8 + lrow8;             // + p*16
    const int bK = ((lane >> 3) & 1) * 4;
    const uint32_t bOffBase = (uint32_t)((128 + bCol) * LP2 + bK) * 4;

    float4 rAv[2][2];                 // A register prefetch slots (AH=0)

    while (true) {
        int m0, n0, kbeg0;
        if (DYN) {
            __syncthreads();                 // prior unit's compute done; smem reusable
            if (tid == 0) s_u = (int)atomicAdd(&g_ctr, 1u);
            __syncthreads();
            int u = s_u;
            if (u >= 79 * 8) return;
            m0 = (u % 79) * 128;
            n0 = 0;
            kbeg0 = (u / 79) * 256;
        } else {
            m0 = blockIdx.y * 128;
            n0 = blockIdx.x * 128;
            kbeg0 = 0;
        }

        const int nch = nchunks;
        const int gm = m0 + lrow;
        const int gn = n0 + lrow;
        const bool mok = (gm < NN);
        const bool nok = (gn < Ntot);

        // ---- issue helpers ----
        auto issueA = [&](int ch, int slot, int st) {
            int kbeg = kbeg0 + ch * 16;
            if (AH == 0) {
                if (mok) {
                    const float* ap = Af + (size_t)gm * lda + kbeg + part * 8;
                    rAv[slot][0] = *(const float4*)ap;
                    rAv[slot][1] = *(const float4*)(ap + 4);
                } else {
                    rAv[slot][0] = make_float4(0.f, 0.f, 0.f, 0.f);
                    rAv[slot][1] = make_float4(0.f, 0.f, 0.f, 0.f);
                }
            } else {
                if (mok) {
                    uint32_t d = sbase + (uint32_t)(st * STAGE_W + lrow * LP2 + part * 4) * 4;
                    CP_ASYNC16(d,      Ahg + (size_t)gm * lda + kbeg + part * 8);
                    CP_ASYNC16(d + 32, Alg + (size_t)gm * lda + kbeg + part * 8);
                }
            }
        };
        auto stsA = [&](int slot, int st) {   // AH=0 only
            uint4 H, L;
            splitpair(rAv[slot][0].x, rAv[slot][0].y, H.x, L.x);
            splitpair(rAv[slot][0].z, rAv[slot][0].w, H.y, L.y);
            splitpair(rAv[slot][1].x, rAv[slot][1].y, H.z, L.z);
            splitpair(rAv[slot][1].z, rAv[slot][1].w, H.w, L.w);
            uint32_t* p = sm + st * STAGE_W + lrow * LP2 + part * 4;
            *(uint4*)p = H;
            *(uint4*)(p + 8) = L;
        };
        auto issueB = [&](int ch, int st) {
            if (nok) {
                int kbeg = kbeg0 + ch * 16;
                uint32_t d = sbase + (uint32_t)(st * STAGE_W + 128 * LP2 + lrow * LP2 + part * 4) * 4;
                CP_ASYNC16(d,      Bth + (size_t)gn * ldb + kbeg + part * 8);
                CP_ASYNC16(d + 32, Btl + (size_t)gn * ldb + kbeg + part * 8);
            }
        };

        float acc[2][8][4];
#pragma unroll
        for (int i = 0; i < 2; i++)
#pragma unroll
            for (int j = 0; j < 8; j++)
#pragma unroll
                for (int q = 0; q < 4; q++) acc[i][j][q] = 0.f;

        // ---- prologue: chunks 0 and 1 in flight ----
        issueA(0, 0, 0); issueB(0, 0); CP_COMMIT();
        issueA(1, 1, 1); issueB(1, 1); CP_COMMIT();
        if (AH == 0) stsA(0, 0);

        // ---- main pipeline ----
        for (int ch = 0; ch < nch; ch++) {
            if (ch + 1 < nch) { CP_WAIT1(); } else { CP_WAIT0(); }
            __syncthreads();

            if (AH == 0 && ch + 1 < nch) stsA((ch + 1) & 1, (ch + 1) % 3);
            if (ch + 2 < nch) {
                issueA(ch + 2, ch & 1, (ch + 2) % 3);
                issueB(ch + 2, (ch + 2) % 3);
                CP_COMMIT();
            }

            // ---- compute chunk ch on stage ch%3 (ldmatrix fragments) ----
            const uint32_t stb = sbase + (uint32_t)((ch % 3) * STAGE_W) * 4;
            uint32_t ah[2][4], al[2][4];
            ldsm4(ah[0], stb + aOff0);
            ldsm4(ah[1], stb + aOff1);
            ldsm4(al[0], stb + aOff0 + 32);
            ldsm4(al[1], stb + aOff1 + 32);
#pragma unroll
            for (int p = 0; p < 4; p++) {
                uint32_t bAddr = stb + bOffBase + (uint32_t)(p * 16 * LP2) * 4;
                uint32_t bh[4], bl[4];
                ldsm4(bh, bAddr);
                ldsm4(bl, bAddr + 32);
                const int nj0 = 2 * p, nj1 = 2 * p + 1;
                mma16(acc[0][nj0], ah[0], bh[0], bh[1]);
                mma16(acc[1][nj0], ah[1], bh[0], bh[1]);
                mma16(acc[0][nj1], ah[0], bh[2], bh[3]);
                mma16(acc[1][nj1], ah[1], bh[2], bh[3]);
                mma16(acc[0][nj0], al[0], bh[0], bh[1]);
                mma16(acc[1][nj0], al[1], bh[0], bh[1]);
                mma16(acc[0][nj1], al[0], bh[2], bh[3]);
                mma16(acc[1][nj1], al[1], bh[2], bh[3]);
                mma16(acc[0][nj0], ah[0], bl[0], bl[1]);
                mma16(acc[1][nj0], ah[1], bl[0], bl[1]);
                mma16(acc[0][nj1], ah[0], bl[2], bl[3]);
                mma16(acc[1][nj1], ah[1], bl[2], bl[3]);
            }
        }

        // ---- epilogue ----
#pragma unroll
        for (int mi = 0; mi < 2; mi++) {
            int r0 = m0 + m_warp + mi * 16 + g;
            int r1 = r0 + 8;
#pragma unroll
            for (int nj = 0; nj < 8; nj++) {
                int gc = n0 + n_warp + nj * 8 + tig * 2;
                if (EPI == 0) {
                    if (r0 < NN) {
                        atomicAdd(&Cf[(size_t)r0 * 128 + gc],     acc[mi][nj][0]);
                        atomicAdd(&Cf[(size_t)r0 * 128 + gc + 1], acc[mi][nj][1]);
                    }
                    if (r1 < NN) {
                        atomicAdd(&Cf[(size_t)r1 * 128 + gc],     acc[mi][nj][2]);
                        atomicAdd(&Cf[(size_t)r1 * 128 + gc + 1], acc[mi][nj][3]);
                    }
                } else {
                    if (gc < 512) {
                        __half2 p0 = __floats2half2_rn(acc[mi][nj][0], acc[mi][nj][1]);
                        __half2 p1 = __floats2half2_rn(acc[mi][nj][2], acc[mi][nj][3]);
                        if (r0 < NN) *(__half2*)&Ch[(size_t)r0 * 512 + gc] = p0;
                        if (r1 < NN) *(__half2*)&Ch[(size_t)r1 * 512 + gc] = p1;
                    } else if (gc < 576) {
                        int rc = gc - 512;
                        if (r0 < NN) {
                            float2 f = make_float2(acc[mi][nj][0], acc[mi][nj][1]);
                            *(float2*)&Cr[(size_t)r0 * 64 + rc] = f;
                        }
                        if (r1 < NN) {
                            float2 f = make_float2(acc[mi][nj][2], acc[mi][nj][3]);
                            *(float2*)&Cr[(size_t)r1 * 64 + rc] = f;
                        }
                    }
                }
            }
        }
        if (!DYN) return;
    }
}

// ---------------- fp32 tiled GEMM for xb2 with fused fp16/fp32 split store ----------------
__global__ void __launch_bounds__(256)
sgemm_split(const float* __restrict__ A, const float* __restrict__ B, int M, int N, int K) {
    __shared__ float As[128][16];
    __shared__ float Bs[16][64];

    const int m0 = blockIdx.y * 128;
    const int n0 = blockIdx.x * 64;
    const int tid = threadIdx.x;
    const int tx = tid & 15;
    const int ty = tid >> 4;
    const int a_row = tid >> 1;
    const int a_col = (tid & 1) * 8;
    const int b_row = tid >> 4;
    const int b_col = (tid & 15) * 4;

    float acc[8][4];
#pragma unroll
    for (int i = 0; i < 8; i++)
#pragma unroll
        for (int j = 0; j < 4; j++) acc[i][j] = 0.0f;

    for (int k0 = 0; k0 < K; k0 += 16) {
        if (m0 + a_row < M) {
            const float* ap = A + (size_t)(m0 + a_row) * K + k0 + a_col;
            *(float4*)&As[a_row][a_col]     = *(const float4*)(ap);
            *(float4*)&As[a_row][a_col + 4] = *(const float4*)(ap + 4);
        } else {
            float4 z = make_float4(0.f, 0.f, 0.f, 0.f);
            *(float4*)&As[a_row][a_col]     = z;
            *(float4*)&As[a_row][a_col + 4] = z;
        }
        if (n0 + b_col + 3 < N) {
            *(float4*)&Bs[b_row][b_col] =
                *(const float4*)(B + (size_t)(k0 + b_row) * N + n0 + b_col);
        } else {
#pragma unroll
            for (int j = 0; j < 4; j++)
                Bs[b_row][b_col + j] =
                    (n0 + b_col + j < N) ? B[(size_t)(k0 + b_row) * N + n0 + b_col + j] : 0.0f;
        }
        __syncthreads();

#pragma unroll
        for (int kk = 0; kk < 16; kk++) {
            float rB[4];
            *(float4*)rB = *(const float4*)&Bs[kk][tx * 4];
#pragma unroll
            for (int i = 0; i < 8; i++) {
                float a = As[ty * 8 + i][kk];
                acc[i][0] += a * rB[0];
                acc[i][1] += a * rB[1];
                acc[i][2] += a * rB[2];
                acc[i][3] += a * rB[3];
            }
        }
        __syncthreads();
    }

#pragma unroll
    for (int i = 0; i < 8; i++) {
        int m = m0 + ty * 8 + i;
        if (m >= M) continue;
#pragma unroll
        for (int j = 0; j < 4; j++) {
            int n = n0 + tx * 4 + j;
            if (n >= N) continue;
            float v = acc[i][j];
            if (n < 160) g_xb2h[(size_t)m * 160 + n] = __float2half(v);
            else g_root2o[(size_t)m * 20 + (n - 160)] = v;
        }
    }
}

// ---------------- layer-1 aggregation (fp16 gathers, packed rec/w, fused epilogue) ------
__global__ void agg1_kernel(const float* __restrict__ comp, const float* __restrict__ bias) {
    int w = (blockIdx.x * blockDim.x + threadIdx.x) >> 5;
    int lane = threadIdx.x & 31;
    if (w >= NN) return;
    int beg = g_off[w];
    int end = g_off[w + 1];

    float ax = 0.f, ay = 0.f;
    int2 rw = (beg < end) ? g_recw[beg] : make_int2(0, 0);
    for (int i = beg; i < end; i++) {
        int src = rw.x & 0xFFFF;
        int r = rw.x >> 16;
        float inv = __int_as_float(rw.y);
        if (i + 1 < end) rw = g_recw[i + 1];
        float4 c0 = *(const float4*)(comp + r * 8);
        float4 c1 = *(const float4*)(comp + r * 8 + 4);
        const __half2* xr = (const __half2*)(g_xb1h + (size_t)src * 512);
        float mx = 0.f, my = 0.f;
        float2 f;
        f = __half22float2(xr[0 * 32 + lane]); mx += c0.x * f.x; my += c0.x * f.y;
        f = __half22float2(xr[1 * 32 + lane]); mx += c0.y * f.x; my += c0.y * f.y;
        f = __half22float2(xr[2 * 32 + lane]); mx += c0.z * f.x; my += c0.z * f.y;
        f = __half22float2(xr[3 * 32 + lane]); mx += c0.w * f.x; my += c0.w * f.y;
        f = __half22float2(xr[4 * 32 + lane]); mx += c1.x * f.x; my += c1.x * f.y;
        f = __half22float2(xr[5 * 32 + lane]); mx += c1.y * f.x; my += c1.y * f.y;
        f = __half22float2(xr[6 * 32 + lane]); mx += c1.z * f.x; my += c1.z * f.y;
        f = __half22float2(xr[7 * 32 + lane]); mx += c1.w * f.x; my += c1.w * f.y;
        ax += inv * mx;
        ay += inv * my;
    }
    int o = lane * 2;
    float r0 = ax + g_root1[w * 64 + o]     + bias[o];
    float r1 = ay + g_root1[w * 64 + o + 1] + bias[o + 1];
    g_h[w * 64 + o]     = fmaxf(r0, 0.f);
    g_h[w * 64 + o + 1] = fmaxf(r1, 0.f);
}

// ---------------- layer-2 aggregation (fp16 gathers, packed rec/w, fused epilogue) ------
__global__ void agg2_kernel(const float* __restrict__ comp, const float* __restrict__ bias,
                            float* __restrict__ out) {
    int w = (blockIdx.x * blockDim.x + threadIdx.x) >> 5;
    int lane = threadIdx.x & 31;
    if (w >= NN) return;
    int beg = g_off[w];
    int end = g_off[w + 1];
    int l = (lane < 20) ? lane : 0;

    float acc = 0.f;
    int2 rw = (beg < end) ? g_recw[beg] : make_int2(0, 0);
    for (int i = beg; i < end; i++) {
        int src = rw.x & 0xFFFF;
        int r = rw.x >> 16;
        float inv = __int_as_float(rw.y);
        if (i + 1 < end) rw = g_recw[i + 1];
        float4 c0 = *(const float4*)(comp + r * 8);
        float4 c1 = *(const float4*)(comp + r * 8 + 4);
        const __half* xr = g_xb2h + (size_t)src * 160;
        float m = 0.f;
        m += c0.x * __half2float(xr[0 * 20 + l]);
        m += c0.y * __half2float(xr[1 * 20 + l]);
        m += c0.z * __half2float(xr[2 * 20 + l]);
        m += c0.w * __half2float(xr[3 * 20 + l]);
        m += c1.x * __half2float(xr[4 * 20 + l]);
        m += c1.y * __half2float(xr[5 * 20 + l]);
        m += c1.z * __half2float(xr[6 * 20 + l]);
        m += c1.w * __half2float(xr[7 * 20 + l]);
        acc += inv * m;
    }
    if (lane < 20) {
        out[w * 20 + lane] = acc + g_root2o[w * 20 + lane] + bias[lane];
    }
}

// ---------------- launch ----------------
extern "C" void kernel_launch(void* const* d_in, const int* in_sizes, int n_in,
                              void* d_out, int out_size) {
    const float* x_drug = (const float*)d_in[0];
    const float* drug_w = (const float*)d_in[1];
    const int*   ei     = (const int*)d_in[2];
    const float* basis1 = (const float*)d_in[3];
    const float* comp1  = (const float*)d_in[4];
    const float* root1  = (const float*)d_in[5];
    const float* bias1  = (const float*)d_in[6];
    const float* basis2 = (const float*)d_in[7];
    const float* comp2  = (const float*)d_in[8];
    const float* root2  = (const float*)d_in[9];
    const float* bias2  = (const float*)d_in[10];
    float* out = (float*)d_out;

    void *px, *pxah, *pxal, *pbwh, *pbwl, *pb1h, *pb1l, *pxb1h, *proot1, *ph, *pb2;
    cudaGetSymbolAddress(&px,     g_x);
    cudaGetSymbolAddress(&pxah,   g_xAh);
    cudaGetSymbolAddress(&pxal,   g_xAl);
    cudaGetSymbolAddress(&pbwh,   g_BtW_hi);
    cudaGetSymbolAddress(&pbwl,   g_BtW_lo);
    cudaGetSymbolAddress(&pb1h,   g_Bt1_hi);
    cudaGetSymbolAddress(&pb1l,   g_Bt1_lo);
    cudaGetSymbolAddress(&pxb1h,  g_xb1h);
    cudaGetSymbolAddress(&proot1, g_root1);
    cudaGetSymbolAddress(&ph,     g_h);
    cudaGetSymbolAddress(&pb2,    g_Bcat2);

    const int SMEM = 3 * STAGE_W * 4;   // 61440 bytes
    cudaFuncSetAttribute(mma_gemm<1, 0, 0>, cudaFuncAttributeMaxDynamicSharedMemorySize, SMEM);
    cudaFuncSetAttribute(mma_gemm<0, 1, 1>, cudaFuncAttributeMaxDynamicSharedMemorySize, SMEM);

    // 0: fused setup (zero + all weight prep)
    setup_all<<<1024, 256>>>(drug_w, basis1, root1, basis2, root2);

    // 1: x = x_drug @ drug_w : pipelined fp16-split mma GEMM
    mma_gemm<1, 0, 0><<<296, 256, SMEM>>>(
        x_drug, nullptr, nullptr, 2048,
        (const __half*)pbwh, (const __half*)pbwl, 2048,
        128, 16, (float*)px, nullptr, nullptr);

    // 2: fused g_x fp16 split + degree count
    cvtx_deg<<<2048, 256>>>(ei);

    // 3: xb1 = x @ [basis1|root1] (profiled launch)
    mma_gemm<0, 1, 1><<<dim3(5, 79), 256, SMEM>>>(
        nullptr, (const __half*)pxah, (const __half*)pxal, 128,
        (const __half*)pb1h, (const __half*)pb1l, 128,
        576, 8, nullptr, (__half*)pxb1h, (float*)proot1);

    scan_kernel<<<1, 1024>>>();                                  // 4
    scatter_kernel<<<(NEDGE + 255) / 256, 256>>>(ei);            // 5

    agg1_kernel<<<(NN * 32 + 255) / 256, 256>>>(comp1, bias1);   // 6

    // 7: xb2 = h @ [basis2|root2] with fused fp16/fp32 split store
    sgemm_split<<<dim3(3, 79), 256>>>((const float*)ph, (const float*)pb2, NN, 180, 64);

    agg2_kernel<<<(NN * 32 + 255) / 256, 256>>>(comp2, bias2, out);  // 8
}

// round 14
// speedup vs baseline: 1.2016x; 1.1040x over previous
#include <cuda_runtime.h>
#include <cuda_fp16.h>
#include <cstdint>

#define NN 10000
#define RR 100
#define EE 5000
#define NEDGE (RR * EE)

// ---------------- scratch (device globals; no allocations) ----------------
__device__ int   g_deg[RR * NN];
__device__ int   g_cnt[NN];
__device__ int   g_off[NN + 1];
__device__ int   g_cur[NN];
__device__ int2  g_recw[NEDGE];           // packed {(r<<16)|src, 1/deg bits}, grouped by dst
__device__ unsigned int g_ctr;            // dynamic unit counter for gemm1
__device__ float g_x[NN * 128];           // x = x_drug @ drug_w (atomic accumulated)
__device__ __half g_xAh[NN * 128];        // x fp16-hi (for xb1 gemm A)
__device__ __half g_xAl[NN * 128];        // x fp16-lo
__device__ __half g_BtW_hi[128 * 2048];   // drug_w^T fp16-hi
__device__ __half g_BtW_lo[128 * 2048];   // drug_w^T fp16-lo
__device__ __half g_Bt1_hi[576 * 128];    // [basis1|root1]^T fp16-hi
__device__ __half g_Bt1_lo[576 * 128];
__device__ __half g_xb1h[NN * 512];       // x @ basis1 (fp16)
__device__ float g_root1[NN * 64];        // x @ root1 (fp32)
__device__ float g_h[NN * 64];            // layer-1 output (post relu)
__device__ float g_Bcat2[64 * 180];       // [basis2 (8x20) | root2 (20)]
__device__ __half g_xb2h[NN * 160];
__device__ float g_root2o[NN * 20];

// ---------------- helpers ----------------
__device__ __forceinline__ uint32_t smem_to_u32(const void* p) {
    uint32_t a;
    asm("{ .reg .u64 t; cvta.to.shared.u64 t, %1; cvt.u32.u64 %0, t; }" : "=r"(a) : "l"(p));
    return a;
}
#define CP_ASYNC16(dst_u32, gptr) \
    asm volatile("cp.async.cg.shared.global [%0], [%1], 16;" :: "r"(dst_u32), "l"(gptr) : "memory")
#define CP_COMMIT() asm volatile("cp.async.commit_group;" ::: "memory")
#define CP_WAIT1()  asm volatile("cp.async.wait_group 1;" ::: "memory")
#define CP_WAIT0()  asm volatile("cp.async.wait_group 0;" ::: "memory")

__device__ __forceinline__ void ldsm4(uint32_t* r, uint32_t addr) {
    asm volatile("ldmatrix.sync.aligned.m8n8.x4.shared.b16 {%0,%1,%2,%3}, [%4];"
        : "=r"(r[0]), "=r"(r[1]), "=r"(r[2]), "=r"(r[3]) : "r"(addr));
}
__device__ __forceinline__ void splitpair(float a, float b, uint32_t& h, uint32_t& l) {
    __half ha = __float2half_rn(a), hb = __float2half_rn(b);
    __half la = __float2half_rn(a - __half2float(ha));
    __half lb = __float2half_rn(b - __half2float(hb));
    __half2 H = __halves2half2(ha, hb), L = __halves2half2(la, lb);
    h = *(uint32_t*)&H;
    l = *(uint32_t*)&L;
}
__device__ __forceinline__ void mma16(float* d, const uint32_t* a, uint32_t b0, uint32_t b1) {
    asm volatile("mma.sync.aligned.m16n8k16.row.col.f32.f16.f16.f32 "
        "{%0,%1,%2,%3}, {%4,%5,%6,%7}, {%8,%9}, {%0,%1,%2,%3};"
        : "+f"(d[0]), "+f"(d[1]), "+f"(d[2]), "+f"(d[3])
        : "r"(a[0]), "r"(a[1]), "r"(a[2]), "r"(a[3]), "r"(b0), "r"(b1));
}

// ---------------- fused setup: zero + all weight prep ----------------
__global__ void setup_all(const float* __restrict__ w,
                          const float* __restrict__ basis1, const float* __restrict__ root1,
                          const float* __restrict__ basis2, const float* __restrict__ root2) {
    int stride = gridDim.x * blockDim.x;
    int i0 = blockIdx.x * blockDim.x + threadIdx.x;
    for (int i = i0; i < RR * NN; i += stride) g_deg[i] = 0;
    for (int i = i0; i < NN; i += stride) g_cnt[i] = 0;
    for (int i = i0; i < NN * 128; i += stride) g_x[i] = 0.0f;
    if (i0 == 0) g_ctr = 0u;
    for (int idx = i0; idx < 2048 * 128; idx += stride) {
        int k = idx >> 7, n = idx & 127;
        float v = w[idx];
        __half h = __float2half_rn(v);
        g_BtW_hi[n * 2048 + k] = h;
        g_BtW_lo[n * 2048 + k] = __float2half_rn(v - __half2float(h));
    }
    for (int idx = i0; idx < 576 * 128; idx += stride) {
        int c = idx >> 7, i = idx & 127;
        float v = (c < 512) ? basis1[(c >> 6) * 128 * 64 + i * 64 + (c & 63)]
                            : root1[i * 64 + (c - 512)];
        __half h = __float2half_rn(v);
        g_Bt1_hi[c * 128 + i] = h;
        g_Bt1_lo[c * 128 + i] = __float2half_rn(v - __half2float(h));
    }
    for (int idx = i0; idx < 64 * 180; idx += stride) {
        int i = idx / 180;
        int c = idx - i * 180;
        g_Bcat2[idx] = (c < 160) ? basis2[(c / 20) * 64 * 20 + i * 20 + (c % 20)]
                                 : root2[i * 20 + (c - 160)];
    }
}

// ---------------- degree + per-dst count (side stream) ----------------
__global__ void deg_kernel(const int* __restrict__ ei) {
    int idx = blockIdx.x * blockDim.x + threadIdx.x;
    if (idx >= NEDGE) return;
    int r = idx / EE;
    int e = idx - r * EE;
    int dst = ei[r * 2 * EE + EE + e];
    atomicAdd(&g_deg[r * NN + dst], 1);
    atomicAdd(&g_cnt[dst], 1);
}

// ---------------- g_x fp32 -> fp16 hi/lo split (main stream) ----------------
__global__ void cvtx_kernel() {
    int idx = blockIdx.x * blockDim.x + threadIdx.x;
    if (idx >= NN * 128) return;
    float v = g_x[idx];
    __half h = __float2half_rn(v);
    g_xAh[idx] = h;
    g_xAl[idx] = __float2half_rn(v - __half2float(h));
}

// ---------------- single-block exclusive scan ----------------
__global__ void scan_kernel() {
    __shared__ int sp[1024];
    int t = threadIdx.x;
    int base = t * 10;
    int loc[10];
    int s = 0;
#pragma unroll
    for (int j = 0; j < 10; j++) {
        int idx = base + j;
        int v = (idx < NN) ? g_cnt[idx] : 0;
        loc[j] = s;
        s += v;
    }
    sp[t] = s;
    __syncthreads();
    for (int off = 1; off < 1024; off <<= 1) {
        int v = (t >= off) ? sp[t - off] : 0;
        __syncthreads();
        sp[t] += v;
        __syncthreads();
    }
    int pre = (t > 0) ? sp[t - 1] : 0;
#pragma unroll
    for (int j = 0; j < 10; j++) {
        int idx = base + j;
        if (idx < NN) {
            int o = pre + loc[j];
            g_off[idx] = o;
            g_cur[idx] = o;
        }
    }
    if (t == 0) g_off[NN] = NEDGE;
}

// ---------------- scatter edges into dst buckets (packed rec + 1/deg) ----------------
__global__ void scatter_kernel(const int* __restrict__ ei) {
    int idx = blockIdx.x * blockDim.x + threadIdx.x;
    if (idx >= NEDGE) return;
    int r = idx / EE;
    int e = idx - r * EE;
    const int* eir = ei + r * 2 * EE;
    int src = eir[e];
    int dst = eir[EE + e];
    int pos = atomicAdd(&g_cur[dst], 1);
    float w = 1.0f / (float)max(g_deg[r * NN + dst], 1);
    g_recw[pos] = make_int2((r << 16) | src, __float_as_int(w));
}

// ================= pipelined mma.sync fp16-split GEMM (3-product, ldmatrix) =================
#define LP2 20
#define STAGE_W (2 * 128 * LP2)

template<int DYN, int EPI, int AH>
__global__ void __launch_bounds__(256, 2)
mma_gemm(const float* __restrict__ Af,
         const __half* __restrict__ Ahg, const __half* __restrict__ Alg, int lda,
         const __half* __restrict__ Bth, const __half* __restrict__ Btl, int ldb,
         int Ntot, int nchunks,
         float* __restrict__ Cf, __half* __restrict__ Ch, float* __restrict__ Cr) {
    extern __shared__ uint32_t sm[];
    const uint32_t sbase = smem_to_u32(sm);
    __shared__ int s_u;

    const int tid = threadIdx.x;
    const int wid = tid >> 5;
    const int lane = tid & 31;
    const int g = lane >> 2;
    const int tig = lane & 3;
    const int m_warp = (wid & 3) * 32;
    const int n_warp = (wid >> 2) * 64;
    const int lrow = tid >> 1;        // 0..127
    const int part = tid & 1;         // 8-element half-row

    // ---- per-lane ldmatrix base offsets ----
    const int lrow8 = lane & 7;
    const int aRow = m_warp + ((lane >> 3) & 1) * 8 + lrow8;       // + mi*16
    const int aK = (lane >> 4) * 4;
    const uint32_t aOff0 = (uint32_t)((aRow)      * LP2 + aK) * 4; // mi=0 (bytes)
    const uint32_t aOff1 = (uint32_t)((aRow + 16) * LP2 + aK) * 4; // mi=1
    const int bCol = n_warp + (lane >> 4) * 8 + lrow8;             // + p*16
    const int bK = ((lane >> 3) & 1) * 4;
    const uint32_t bOffBase = (uint32_t)((128 + bCol) * LP2 + bK) * 4;

    float4 rAv[2][2];                 // A register prefetch slots (AH=0)

    while (true) {
        int m0, n0, kbeg0;
        if (DYN) {
            __syncthreads();                 // prior unit's compute done; smem reusable
            if (tid == 0) s_u = (int)atomicAdd(&g_ctr, 1u);
            __syncthreads();
            int u = s_u;
            if (u >= 79 * 8) return;
            m0 = (u % 79) * 128;
            n0 = 0;
            kbeg0 = (u / 79) * 256;
        } else {
            m0 = blockIdx.y * 128;
            n0 = blockIdx.x * 128;
            kbeg0 = 0;
        }

        const int nch = nchunks;
        const int gm = m0 + lrow;
        const int gn = n0 + lrow;
        const bool mok = (gm < NN);
        const bool nok = (gn < Ntot);

        // ---- issue helpers ----
        auto issueA = [&](int ch, int slot, int st) {
            int kbeg = kbeg0 + ch * 16;
            if (AH == 0) {
                if (mok) {
                    const float* ap = Af + (size_t)gm * lda + kbeg + part * 8;
                    rAv[slot][0] = *(const float4*)ap;
                    rAv[slot][1] = *(const float4*)(ap + 4);
                } else {
                    rAv[slot][0] = make_float4(0.f, 0.f, 0.f, 0.f);
                    rAv[slot][1] = make_float4(0.f, 0.f, 0.f, 0.f);
                }
            } else {
                if (mok) {
                    uint32_t d = sbase + (uint32_t)(st * STAGE_W + lrow * LP2 + part * 4) * 4;
                    CP_ASYNC16(d,      Ahg + (size_t)gm * lda + kbeg + part * 8);
                    CP_ASYNC16(d + 32, Alg + (size_t)gm * lda + kbeg + part * 8);
                }
            }
        };
        auto stsA = [&](int slot, int st) {   // AH=0 only
            uint4 H, L;
            splitpair(rAv[slot][0].x, rAv[slot][0].y, H.x, L.x);
            splitpair(rAv[slot][0].z, rAv[slot][0].w, H.y, L.y);
            splitpair(rAv[slot][1].x, rAv[slot][1].y, H.z, L.z);
            splitpair(rAv[slot][1].z, rAv[slot][1].w, H.w, L.w);
            uint32_t* p = sm + st * STAGE_W + lrow * LP2 + part * 4;
            *(uint4*)p = H;
            *(uint4*)(p + 8) = L;
        };
        auto issueB = [&](int ch, int st) {
            if (nok) {
                int kbeg = kbeg0 + ch * 16;
                uint32_t d = sbase + (uint32_t)(st * STAGE_W + 128 * LP2 + lrow * LP2 + part * 4) * 4;
                CP_ASYNC16(d,      Bth + (size_t)gn * ldb + kbeg + part * 8);
                CP_ASYNC16(d + 32, Btl + (size_t)gn * ldb + kbeg + part * 8);
            }
        };

        float acc[2][8][4];
#pragma unroll
        for (int i = 0; i < 2; i++)
#pragma unroll
            for (int j = 0; j < 8; j++)
#pragma unroll
                for (int q = 0; q < 4; q++) acc[i][j][q] = 0.f;

        // ---- prologue: chunks 0 and 1 in flight ----
        issueA(0, 0, 0); issueB(0, 0); CP_COMMIT();
        issueA(1, 1, 1); issueB(1, 1); CP_COMMIT();
        if (AH == 0) stsA(0, 0);

        // ---- main pipeline ----
        for (int ch = 0; ch < nch; ch++) {
            if (ch + 1 < nch) { CP_WAIT1(); } else { CP_WAIT0(); }
            __syncthreads();

            if (AH == 0 && ch + 1 < nch) stsA((ch + 1) & 1, (ch + 1) % 3);
            if (ch + 2 < nch) {
                issueA(ch + 2, ch & 1, (ch + 2) % 3);
                issueB(ch + 2, (ch + 2) % 3);
                CP_COMMIT();
            }

            // ---- compute chunk ch on stage ch%3 (ldmatrix fragments) ----
            const uint32_t stb = sbase + (uint32_t)((ch % 3) * STAGE_W) * 4;
            uint32_t ah[2][4], al[2][4];
            ldsm4(ah[0], stb + aOff0);
            ldsm4(ah[1], stb + aOff1);
            ldsm4(al[0], stb + aOff0 + 32);
            ldsm4(al[1], stb + aOff1 + 32);
#pragma unroll
            for (int p = 0; p < 4; p++) {
                uint32_t bAddr = stb + bOffBase + (uint32_t)(p * 16 * LP2) * 4;
                uint32_t bh[4], bl[4];
                ldsm4(bh, bAddr);
                ldsm4(bl, bAddr + 32);
                const int nj0 = 2 * p, nj1 = 2 * p + 1;
                mma16(acc[0][nj0], ah[0], bh[0], bh[1]);
                mma16(acc[1][nj0], ah[1], bh[0], bh[1]);
                mma16(acc[0][nj1], ah[0], bh[2], bh[3]);
                mma16(acc[1][nj1], ah[1], bh[2], bh[3]);
                mma16(acc[0][nj0], al[0], bh[0], bh[1]);
                mma16(acc[1][nj0], al[1], bh[0], bh[1]);
                mma16(acc[0][nj1], al[0], bh[2], bh[3]);
                mma16(acc[1][nj1], al[1], bh[2], bh[3]);
                mma16(acc[0][nj0], ah[0], bl[0], bl[1]);
                mma16(acc[1][nj0], ah[1], bl[0], bl[1]);
                mma16(acc[0][nj1], ah[0], bl[2], bl[3]);
                mma16(acc[1][nj1], ah[1], bl[2], bl[3]);
            }
        }

        // ---- epilogue ----
#pragma unroll
        for (int mi = 0; mi < 2; mi++) {
            int r0 = m0 + m_warp + mi * 16 + g;
            int r1 = r0 + 8;
#pragma unroll
            for (int nj = 0; nj < 8; nj++) {
                int gc = n0 + n_warp + nj * 8 + tig * 2;
                if (EPI == 0) {
                    if (r0 < NN) {
                        atomicAdd(&Cf[(size_t)r0 * 128 + gc],     acc[mi][nj][0]);
                        atomicAdd(&Cf[(size_t)r0 * 128 + gc + 1], acc[mi][nj][1]);
                    }
                    if (r1 < NN) {
                        atomicAdd(&Cf[(size_t)r1 * 128 + gc],     acc[mi][nj][2]);
                        atomicAdd(&Cf[(size_t)r1 * 128 + gc + 1], acc[mi][nj][3]);
                    }
                } else {
                    if (gc < 512) {
                        __half2 p0 = __floats2half2_rn(acc[mi][nj][0], acc[mi][nj][1]);
                        __half2 p1 = __floats2half2_rn(acc[mi][nj][2], acc[mi][nj][3]);
                        if (r0 < NN) *(__half2*)&Ch[(size_t)r0 * 512 + gc] = p0;
                        if (r1 < NN) *(__half2*)&Ch[(size_t)r1 * 512 + gc] = p1;
                    } else if (gc < 576) {
                        int rc = gc - 512;
                        if (r0 < NN) {
                            float2 f = make_float2(acc[mi][nj][0], acc[mi][nj][1]);
                            *(float2*)&Cr[(size_t)r0 * 64 + rc] = f;
                        }
                        if (r1 < NN) {
                            float2 f = make_float2(acc[mi][nj][2], acc[mi][nj][3]);
                            *(float2*)&Cr[(size_t)r1 * 64 + rc] = f;
                        }
                    }
                }
            }
        }
        if (!DYN) return;
    }
}

// ---------------- fp32 tiled GEMM for xb2 with fused fp16/fp32 split store ----------------
__global__ void __launch_bounds__(256)
sgemm_split(const float* __restrict__ A, const float* __restrict__ B, int M, int N, int K) {
    __shared__ float As[128][16];
    __shared__ float Bs[16][64];

    const int m0 = blockIdx.y * 128;
    const int n0 = blockIdx.x * 64;
    const int tid = threadIdx.x;
    const int tx = tid & 15;
    const int ty = tid >> 4;
    const int a_row = tid >> 1;
    const int a_col = (tid & 1) * 8;
    const int b_row = tid >> 4;
    const int b_col = (tid & 15) * 4;

    float acc[8][4];
#pragma unroll
    for (int i = 0; i < 8; i++)
#pragma unroll
        for (int j = 0; j < 4; j++) acc[i][j] = 0.0f;

    for (int k0 = 0; k0 < K; k0 += 16) {
        if (m0 + a_row < M) {
            const float* ap = A + (size_t)(m0 + a_row) * K + k0 + a_col;
            *(float4*)&As[a_row][a_col]     = *(const float4*)(ap);
            *(float4*)&As[a_row][a_col + 4] = *(const float4*)(ap + 4);
        } else {
            float4 z = make_float4(0.f, 0.f, 0.f, 0.f);
            *(float4*)&As[a_row][a_col]     = z;
            *(float4*)&As[a_row][a_col + 4] = z;
        }
        if (n0 + b_col + 3 < N) {
            *(float4*)&Bs[b_row][b_col] =
                *(const float4*)(B + (size_t)(k0 + b_row) * N + n0 + b_col);
        } else {
#pragma unroll
            for (int j = 0; j < 4; j++)
                Bs[b_row][b_col + j] =
                    (n0 + b_col + j < N) ? B[(size_t)(k0 + b_row) * N + n0 + b_col + j] : 0.0f;
        }
        __syncthreads();

#pragma unroll
        for (int kk = 0; kk < 16; kk++) {
            float rB[4];
            *(float4*)rB = *(const float4*)&Bs[kk][tx * 4];
#pragma unroll
            for (int i = 0; i < 8; i++) {
                float a = As[ty * 8 + i][kk];
                acc[i][0] += a * rB[0];
                acc[i][1] += a * rB[1];
                acc[i][2] += a * rB[2];
                acc[i][3] += a * rB[3];
            }
        }
        __syncthreads();
    }

#pragma unroll
    for (int i = 0; i < 8; i++) {
        int m = m0 + ty * 8 + i;
        if (m >= M) continue;
#pragma unroll
        for (int j = 0; j < 4; j++) {
            int n = n0 + tx * 4 + j;
            if (n >= N) continue;
            float v = acc[i][j];
            if (n < 160) g_xb2h[(size_t)m * 160 + n] = __float2half(v);
            else g_root2o[(size_t)m * 20 + (n - 160)] = v;
        }
    }
}

// ---------------- layer-1 aggregation (fp16 gathers, packed rec/w, fused epilogue) ------
__global__ void agg1_kernel(const float* __restrict__ comp, const float* __restrict__ bias) {
    int w = (blockIdx.x * blockDim.x + threadIdx.x) >> 5;
    int lane = threadIdx.x & 31;
    if (w >= NN) return;
    int beg = g_off[w];
    int end = g_off[w + 1];

    float ax = 0.f, ay = 0.f;
    int2 rw = (beg < end) ? g_recw[beg] : make_int2(0, 0);
    for (int i = beg; i < end; i++) {
        int src = rw.x & 0xFFFF;
        int r = rw.x >> 16;
        float inv = __int_as_float(rw.y);
        if (i + 1 < end) rw = g_recw[i + 1];
        float4 c0 = *(const float4*)(comp + r * 8);
        float4 c1 = *(const float4*)(comp + r * 8 + 4);
        const __half2* xr = (const __half2*)(g_xb1h + (size_t)src * 512);
        float mx = 0.f, my = 0.f;
        float2 f;
        f = __half22float2(xr[0 * 32 + lane]); mx += c0.x * f.x; my += c0.x * f.y;
        f = __half22float2(xr[1 * 32 + lane]); mx += c0.y * f.x; my += c0.y * f.y;
        f = __half22float2(xr[2 * 32 + lane]); mx += c0.z * f.x; my += c0.z * f.y;
        f = __half22float2(xr[3 * 32 + lane]); mx += c0.w * f.x; my += c0.w * f.y;
        f = __half22float2(xr[4 * 32 + lane]); mx += c1.x * f.x; my += c1.x * f.y;
        f = __half22float2(xr[5 * 32 + lane]); mx += c1.y * f.x; my += c1.y * f.y;
        f = __half22float2(xr[6 * 32 + lane]); mx += c1.z * f.x; my += c1.z * f.y;
        f = __half22float2(xr[7 * 32 + lane]); mx += c1.w * f.x; my += c1.w * f.y;
        ax += inv * mx;
        ay += inv * my;
    }
    int o = lane * 2;
    float r0 = ax + g_root1[w * 64 + o]     + bias[o];
    float r1 = ay + g_root1[w * 64 + o + 1] + bias[o + 1];
    g_h[w * 64 + o]     = fmaxf(r0, 0.f);
    g_h[w * 64 + o + 1] = fmaxf(r1, 0.f);
}

// ---------------- layer-2 aggregation (fp16 gathers, packed rec/w, fused epilogue) ------
__global__ void agg2_kernel(const float* __restrict__ comp, const float* __restrict__ bias,
                            float* __restrict__ out) {
    int w = (blockIdx.x * blockDim.x + threadIdx.x) >> 5;
    int lane = threadIdx.x & 31;
    if (w >= NN) return;
    int beg = g_off[w];
    int end = g_off[w + 1];
    int l = (lane < 20) ? lane : 0;

    float acc = 0.f;
    int2 rw = (beg < end) ? g_recw[beg] : make_int2(0, 0);
    for (int i = beg; i < end; i++) {
        int src = rw.x & 0xFFFF;
        int r = rw.x >> 16;
        float inv = __int_as_float(rw.y);
        if (i + 1 < end) rw = g_recw[i + 1];
        float4 c0 = *(const float4*)(comp + r * 8);
        float4 c1 = *(const float4*)(comp + r * 8 + 4);
        const __half* xr = g_xb2h + (size_t)src * 160;
        float m = 0.f;
        m += c0.x * __half2float(xr[0 * 20 + l]);
        m += c0.y * __half2float(xr[1 * 20 + l]);
        m += c0.z * __half2float(xr[2 * 20 + l]);
        m += c0.w * __half2float(xr[3 * 20 + l]);
        m += c1.x * __half2float(xr[4 * 20 + l]);
        m += c1.y * __half2float(xr[5 * 20 + l]);
        m += c1.z * __half2float(xr[6 * 20 + l]);
        m += c1.w * __half2float(xr[7 * 20 + l]);
        acc += inv * m;
    }
    if (lane < 20) {
        out[w * 20 + lane] = acc + g_root2o[w * 20 + lane] + bias[lane];
    }
}

// ---------------- launch (two-stream capture fork for edge prep) ----------------
extern "C" void kernel_launch(void* const* d_in, const int* in_sizes, int n_in,
                              void* d_out, int out_size) {
    const float* x_drug = (const float*)d_in[0];
    const float* drug_w = (const float*)d_in[1];
    const int*   ei     = (const int*)d_in[2];
    const float* basis1 = (const float*)d_in[3];
    const float* comp1  = (const float*)d_in[4];
    const float* root1  = (const float*)d_in[5];
    const float* bias1  = (const float*)d_in[6];
    const float* basis2 = (const float*)d_in[7];
    const float* comp2  = (const float*)d_in[8];
    const float* root2  = (const float*)d_in[9];
    const float* bias2  = (const float*)d_in[10];
    float* out = (float*)d_out;

    void *px, *pxah, *pxal, *pbwh, *pbwl, *pb1h, *pb1l, *pxb1h, *proot1, *ph, *pb2;
    cudaGetSymbolAddress(&px,     g_x);
    cudaGetSymbolAddress(&pxah,   g_xAh);
    cudaGetSymbolAddress(&pxal,   g_xAl);
    cudaGetSymbolAddress(&pbwh,   g_BtW_hi);
    cudaGetSymbolAddress(&pbwl,   g_BtW_lo);
    cudaGetSymbolAddress(&pb1h,   g_Bt1_hi);
    cudaGetSymbolAddress(&pb1l,   g_Bt1_lo);
    cudaGetSymbolAddress(&pxb1h,  g_xb1h);
    cudaGetSymbolAddress(&proot1, g_root1);
    cudaGetSymbolAddress(&ph,     g_h);
    cudaGetSymbolAddress(&pb2,    g_Bcat2);

    const int SMEM = 3 * STAGE_W * 4;   // 61440 bytes
    cudaFuncSetAttribute(mma_gemm<1, 0, 0>, cudaFuncAttributeMaxDynamicSharedMemorySize, SMEM);
    cudaFuncSetAttribute(mma_gemm<0, 1, 1>, cudaFuncAttributeMaxDynamicSharedMemorySize, SMEM);

    // Host-side stream/event objects, created once (no device memory involved;
    // identical launched work every call).
    static cudaStream_t sB = nullptr;
    static cudaEvent_t evFork = nullptr, evJoin = nullptr;
    if (sB == nullptr) {
        cudaStreamCreateWithFlags(&sB, cudaStreamNonBlocking);
        cudaEventCreateWithFlags(&evFork, cudaEventDisableTiming);
        cudaEventCreateWithFlags(&evJoin, cudaEventDisableTiming);
    }

    // main: fused setup (zero + weight prep)
    setup_all<<<1024, 256>>>(drug_w, basis1, root1, basis2, root2);

    // fork edge-prep chain onto side stream (depends only on setup_all)
    cudaEventRecord(evFork, 0);
    cudaStreamWaitEvent(sB, evFork, 0);
    deg_kernel<<<(NEDGE + 255) / 256, 256, 0, sB>>>(ei);
    scan_kernel<<<1, 1024, 0, sB>>>();
    scatter_kernel<<<(NEDGE + 255) / 256, 256, 0, sB>>>(ei);
    cudaEventRecord(evJoin, sB);

    // main: x = x_drug @ drug_w (overlaps with edge prep)
    mma_gemm<1, 0, 0><<<296, 256, SMEM>>>(
        x_drug, nullptr, nullptr, 2048,
        (const __half*)pbwh, (const __half*)pbwl, 2048,
        128, 16, (float*)px, nullptr, nullptr);

    // main: g_x -> fp16 hi/lo
    cvtx_kernel<<<(NN * 128 + 255) / 256, 256>>>();

    // main: xb1 = x @ [basis1|root1]
    mma_gemm<0, 1, 1><<<dim3(5, 79), 256, SMEM>>>(
        nullptr, (const __half*)pxah, (const __half*)pxal, 128,
        (const __half*)pb1h, (const __half*)pb1l, 128,
        576, 8, nullptr, (__half*)pxb1h, (float*)proot1);

    // join: agg1 needs both the GEMM chain and the edge-prep chain
    cudaStreamWaitEvent(0, evJoin, 0);
    agg1_kernel<<<(NN * 32 + 255) / 256, 256>>>(comp1, bias1);

    // main: xb2 = h @ [basis2|root2] with fused split store
    sgemm_split<<<dim3(3, 79), 256>>>((const float*)ph, (const float*)pb2, NN, 180, 64);

    // main: layer-2 aggregation -> out
    agg2_kernel<<<(NN * 32 + 255) / 256, 256>>>(comp2, bias2, out);
}

// round 15
// speedup vs baseline: 1.2117x; 1.0084x over previous
#include <cuda_runtime.h>
#include <cuda_fp16.h>
#include <cstdint>

#define NN 10000
#define RR 100
#define EE 5000
#define NEDGE (RR * EE)

// ---------------- scratch (device globals; no allocations) ----------------
__device__ int   g_deg[RR * NN];
__device__ int   g_cnt[NN];
__device__ int   g_off[NN + 1];
__device__ int   g_cur[NN];
__device__ int2  g_recw[NEDGE];           // packed {(r<<16)|src, 1/deg bits}, grouped by dst
__device__ unsigned int g_ctr;            // dynamic unit counter for gemm1
__device__ float g_x[NN * 128];           // x = x_drug @ drug_w (atomic accumulated)
__device__ __half g_BtW_hi[128 * 2048];   // drug_w^T fp16-hi
__device__ __half g_BtW_lo[128 * 2048];   // drug_w^T fp16-lo
__device__ __half g_Bt1_hi[576 * 128];    // [basis1|root1]^T fp16-hi
__device__ __half g_Bt1_lo[576 * 128];
__device__ __half g_xb1h[NN * 512];       // x @ basis1 (fp16)
__device__ float g_root1[NN * 64];        // x @ root1 (fp32)
__device__ float g_h[NN * 64];            // layer-1 output (post relu)
__device__ float g_Bcat2[64 * 180];       // [basis2 (8x20) | root2 (20)]
__device__ __half g_xb2h[NN * 160];
__device__ float g_root2o[NN * 20];

// ---------------- helpers ----------------
__device__ __forceinline__ uint32_t smem_to_u32(const void* p) {
    uint32_t a;
    asm("{ .reg .u64 t; cvta.to.shared.u64 t, %1; cvt.u32.u64 %0, t; }" : "=r"(a) : "l"(p));
    return a;
}
#define CP_ASYNC16(dst_u32, gptr) \
    asm volatile("cp.async.cg.shared.global [%0], [%1], 16;" :: "r"(dst_u32), "l"(gptr) : "memory")
#define CP_COMMIT() asm volatile("cp.async.commit_group;" ::: "memory")
#define CP_WAIT1()  asm volatile("cp.async.wait_group 1;" ::: "memory")
#define CP_WAIT0()  asm volatile("cp.async.wait_group 0;" ::: "memory")

__device__ __forceinline__ void ldsm4(uint32_t* r, uint32_t addr) {
    asm volatile("ldmatrix.sync.aligned.m8n8.x4.shared.b16 {%0,%1,%2,%3}, [%4];"
        : "=r"(r[0]), "=r"(r[1]), "=r"(r[2]), "=r"(r[3]) : "r"(addr));
}
__device__ __forceinline__ void splitpair(float a, float b, uint32_t& h, uint32_t& l) {
    __half ha = __float2half_rn(a), hb = __float2half_rn(b);
    __half la = __float2half_rn(a - __half2float(ha));
    __half lb = __float2half_rn(b - __half2float(hb));
    __half2 H = __halves2half2(ha, hb), L = __halves2half2(la, lb);
    h = *(uint32_t*)&H;
    l = *(uint32_t*)&L;
}
__device__ __forceinline__ void mma16(float* d, const uint32_t* a, uint32_t b0, uint32_t b1) {
    asm volatile("mma.sync.aligned.m16n8k16.row.col.f32.f16.f16.f32 "
        "{%0,%1,%2,%3}, {%4,%5,%6,%7}, {%8,%9}, {%0,%1,%2,%3};"
        : "+f"(d[0]), "+f"(d[1]), "+f"(d[2]), "+f"(d[3])
        : "r"(a[0]), "r"(a[1]), "r"(a[2]), "r"(a[3]), "r"(b0), "r"(b1));
}

// ---------------- fused setup: zero + all weight prep ----------------
__global__ void setup_all(const float* __restrict__ w,
                          const float* __restrict__ basis1, const float* __restrict__ root1,
                          const float* __restrict__ basis2, const float* __restrict__ root2) {
    int stride = gridDim.x * blockDim.x;
    int i0 = blockIdx.x * blockDim.x + threadIdx.x;
    for (int i = i0; i < RR * NN; i += stride) g_deg[i] = 0;
    for (int i = i0; i < NN; i += stride) g_cnt[i] = 0;
    for (int i = i0; i < NN * 128; i += stride) g_x[i] = 0.0f;
    if (i0 == 0) g_ctr = 0u;
    for (int idx = i0; idx < 2048 * 128; idx += stride) {
        int k = idx >> 7, n = idx & 127;
        float v = w[idx];
        __half h = __float2half_rn(v);
        g_BtW_hi[n * 2048 + k] = h;
        g_BtW_lo[n * 2048 + k] = __float2half_rn(v - __half2float(h));
    }
    for (int idx = i0; idx < 576 * 128; idx += stride) {
        int c = idx >> 7, i = idx & 127;
        float v = (c < 512) ? basis1[(c >> 6) * 128 * 64 + i * 64 + (c & 63)]
                            : root1[i * 64 + (c - 512)];
        __half h = __float2half_rn(v);
        g_Bt1_hi[c * 128 + i] = h;
        g_Bt1_lo[c * 128 + i] = __float2half_rn(v - __half2float(h));
    }
    for (int idx = i0; idx < 64 * 180; idx += stride) {
        int i = idx / 180;
        int c = idx - i * 180;
        g_Bcat2[idx] = (c < 160) ? basis2[(c / 20) * 64 * 20 + i * 20 + (c % 20)]
                                 : root2[i * 20 + (c - 160)];
    }
}

// ---------------- degree + per-dst count (side stream) ----------------
__global__ void deg_kernel(const int* __restrict__ ei) {
    int idx = blockIdx.x * blockDim.x + threadIdx.x;
    if (idx >= NEDGE) return;
    int r = idx / EE;
    int e = idx - r * EE;
    int dst = ei[r * 2 * EE + EE + e];
    atomicAdd(&g_deg[r * NN + dst], 1);
    atomicAdd(&g_cnt[dst], 1);
}

// ---------------- single-block exclusive scan ----------------
__global__ void scan_kernel() {
    __shared__ int sp[1024];
    int t = threadIdx.x;
    int base = t * 10;
    int loc[10];
    int s = 0;
#pragma unroll
    for (int j = 0; j < 10; j++) {
        int idx = base + j;
        int v = (idx < NN) ? g_cnt[idx] : 0;
        loc[j] = s;
        s += v;
    }
    sp[t] = s;
    __syncthreads();
    for (int off = 1; off < 1024; off <<= 1) {
        int v = (t >= off) ? sp[t - off] : 0;
        __syncthreads();
        sp[t] += v;
        __syncthreads();
    }
    int pre = (t > 0) ? sp[t - 1] : 0;
#pragma unroll
    for (int j = 0; j < 10; j++) {
        int idx = base + j;
        if (idx < NN) {
            int o = pre + loc[j];
            g_off[idx] = o;
            g_cur[idx] = o;
        }
    }
    if (t == 0) g_off[NN] = NEDGE;
}

// ---------------- scatter edges into dst buckets (packed rec + 1/deg) ----------------
__global__ void scatter_kernel(const int* __restrict__ ei) {
    int idx = blockIdx.x * blockDim.x + threadIdx.x;
    if (idx >= NEDGE) return;
    int r = idx / EE;
    int e = idx - r * EE;
    const int* eir = ei + r * 2 * EE;
    int src = eir[e];
    int dst = eir[EE + e];
    int pos = atomicAdd(&g_cur[dst], 1);
    float w = 1.0f / (float)max(g_deg[r * NN + dst], 1);
    g_recw[pos] = make_int2((r << 16) | src, __float_as_int(w));
}

// ================= pipelined mma.sync fp16-split GEMM (3-product, ldmatrix) =================
#define LP2 20
#define STAGE_W (2 * 128 * LP2)

template<int DYN, int EPI, int AH>
__global__ void __launch_bounds__(256, 2)
mma_gemm(const float* __restrict__ Af,
         const __half* __restrict__ Ahg, const __half* __restrict__ Alg, int lda,
         const __half* __restrict__ Bth, const __half* __restrict__ Btl, int ldb,
         int Ntot, int nchunks,
         float* __restrict__ Cf, __half* __restrict__ Ch, float* __restrict__ Cr) {
    extern __shared__ uint32_t sm[];
    const uint32_t sbase = smem_to_u32(sm);
    __shared__ int s_u;

    const int tid = threadIdx.x;
    const int wid = tid >> 5;
    const int lane = tid & 31;
    const int g = lane >> 2;
    const int tig = lane & 3;
    const int m_warp = (wid & 3) * 32;
    const int n_warp = (wid >> 2) * 64;
    const int lrow = tid >> 1;        // 0..127
    const int part = tid & 1;         // 8-element half-row

    // ---- per-lane ldmatrix base offsets ----
    const int lrow8 = lane & 7;
    const int aRow = m_warp + ((lane >> 3) & 1) * 8 + lrow8;       // + mi*16
    const int aK = (lane >> 4) * 4;
    const uint32_t aOff0 = (uint32_t)((aRow)      * LP2 + aK) * 4; // mi=0 (bytes)
    const uint32_t aOff1 = (uint32_t)((aRow + 16) * LP2 + aK) * 4; // mi=1
    const int bCol = n_warp + (lane >> 4) * 8 + lrow8;             // + p*16
    const int bK = ((lane >> 3) & 1) * 4;
    const uint32_t bOffBase = (uint32_t)((128 + bCol) * LP2 + bK) * 4;

    float4 rAv[2][2];                 // A register prefetch slots (AH=0)

    while (true) {
        int m0, n0, kbeg0;
        if (DYN) {
            __syncthreads();                 // prior unit's compute done; smem reusable
            if (tid == 0) s_u = (int)atomicAdd(&g_ctr, 1u);
            __syncthreads();
            int u = s_u;
            if (u >= 79 * 8) return;
            m0 = (u % 79) * 128;
            n0 = 0;
            kbeg0 = (u / 79) * 256;
        } else {
            m0 = blockIdx.y * 128;
            n0 = blockIdx.x * 128;
            kbeg0 = 0;
        }

        const int nch = nchunks;
        const int gm = m0 + lrow;
        const int gn = n0 + lrow;
        const bool mok = (gm < NN);
        const bool nok = (gn < Ntot);

        // ---- issue helpers ----
        auto issueA = [&](int ch, int slot, int st) {
            int kbeg = kbeg0 + ch * 16;
            if (AH == 0) {
                if (mok) {
                    const float* ap = Af + (size_t)gm * lda + kbeg + part * 8;
                    rAv[slot][0] = *(const float4*)ap;
                    rAv[slot][1] = *(const float4*)(ap + 4);
                } else {
                    rAv[slot][0] = make_float4(0.f, 0.f, 0.f, 0.f);
                    rAv[slot][1] = make_float4(0.f, 0.f, 0.f, 0.f);
                }
            } else {
                if (mok) {
                    uint32_t d = sbase + (uint32_t)(st * STAGE_W + lrow * LP2 + part * 4) * 4;
                    CP_ASYNC16(d,      Ahg + (size_t)gm * lda + kbeg + part * 8);
                    CP_ASYNC16(d + 32, Alg + (size_t)gm * lda + kbeg + part * 8);
                }
            }
        };
        auto stsA = [&](int slot, int st) {   // AH=0 only
            uint4 H, L;
            splitpair(rAv[slot][0].x, rAv[slot][0].y, H.x, L.x);
            splitpair(rAv[slot][0].z, rAv[slot][0].w, H.y, L.y);
            splitpair(rAv[slot][1].x, rAv[slot][1].y, H.z, L.z);
            splitpair(rAv[slot][1].z, rAv[slot][1].w, H.w, L.w);
            uint32_t* p = sm + st * STAGE_W + lrow * LP2 + part * 4;
            *(uint4*)p = H;
            *(uint4*)(p + 8) = L;
        };
        auto issueB = [&](int ch, int st) {
            if (nok) {
                int kbeg = kbeg0 + ch * 16;
                uint32_t d = sbase + (uint32_t)(st * STAGE_W + 128 * LP2 + lrow * LP2 + part * 4) * 4;
                CP_ASYNC16(d,      Bth + (size_t)gn * ldb + kbeg + part * 8);
                CP_ASYNC16(d + 32, Btl + (size_t)gn * ldb + kbeg + part * 8);
            }
        };

        float acc[2][8][4];
#pragma unroll
        for (int i = 0; i < 2; i++)
#pragma unroll
            for (int j = 0; j < 8; j++)
#pragma unroll
                for (int q = 0; q < 4; q++) acc[i][j][q] = 0.f;

        // ---- prologue: chunks 0 and 1 in flight ----
        issueA(0, 0, 0); issueB(0, 0); CP_COMMIT();
        issueA(1, 1, 1); issueB(1, 1); CP_COMMIT();
        if (AH == 0) stsA(0, 0);

        // ---- main pipeline ----
        for (int ch = 0; ch < nch; ch++) {
            if (ch + 1 < nch) { CP_WAIT1(); } else { CP_WAIT0(); }
            __syncthreads();

            if (AH == 0 && ch + 1 < nch) stsA((ch + 1) & 1, (ch + 1) % 3);
            if (ch + 2 < nch) {
                issueA(ch + 2, ch & 1, (ch + 2) % 3);
                issueB(ch + 2, (ch + 2) % 3);
                CP_COMMIT();
            }

            // ---- compute chunk ch on stage ch%3 (ldmatrix fragments) ----
            const uint32_t stb = sbase + (uint32_t)((ch % 3) * STAGE_W) * 4;
            uint32_t ah[2][4], al[2][4];
            ldsm4(ah[0], stb + aOff0);
            ldsm4(ah[1], stb + aOff1);
            ldsm4(al[0], stb + aOff0 + 32);
            ldsm4(al[1], stb + aOff1 + 32);
#pragma unroll
            for (int p = 0; p < 4; p++) {
                uint32_t bAddr = stb + bOffBase + (uint32_t)(p * 16 * LP2) * 4;
                uint32_t bh[4], bl[4];
                ldsm4(bh, bAddr);
                ldsm4(bl, bAddr + 32);
                const int nj0 = 2 * p, nj1 = 2 * p + 1;
                mma16(acc[0][nj0], ah[0], bh[0], bh[1]);
                mma16(acc[1][nj0], ah[1], bh[0], bh[1]);
                mma16(acc[0][nj1], ah[0], bh[2], bh[3]);
                mma16(acc[1][nj1], ah[1], bh[2], bh[3]);
                mma16(acc[0][nj0], al[0], bh[0], bh[1]);
                mma16(acc[1][nj0], al[1], bh[0], bh[1]);
                mma16(acc[0][nj1], al[0], bh[2], bh[3]);
                mma16(acc[1][nj1], al[1], bh[2], bh[3]);
                mma16(acc[0][nj0], ah[0], bl[0], bl[1]);
                mma16(acc[1][nj0], ah[1], bl[0], bl[1]);
                mma16(acc[0][nj1], ah[0], bl[2], bl[3]);
                mma16(acc[1][nj1], ah[1], bl[2], bl[3]);
            }
        }

        // ---- epilogue ----
#pragma unroll
        for (int mi = 0; mi < 2; mi++) {
            int r0 = m0 + m_warp + mi * 16 + g;
            int r1 = r0 + 8;
#pragma unroll
            for (int nj = 0; nj < 8; nj++) {
                int gc = n0 + n_warp + nj * 8 + tig * 2;
                if (EPI == 0) {
                    if (r0 < NN) {
                        atomicAdd(&Cf[(size_t)r0 * 128 + gc],     acc[mi][nj][0]);
                        atomicAdd(&Cf[(size_t)r0 * 128 + gc + 1], acc[mi][nj][1]);
                    }
                    if (r1 < NN) {
                        atomicAdd(&Cf[(size_t)r1 * 128 + gc],     acc[mi][nj][2]);
                        atomicAdd(&Cf[(size_t)r1 * 128 + gc + 1], acc[mi][nj][3]);
                    }
                } else {
                    if (gc < 512) {
                        __half2 p0 = __floats2half2_rn(acc[mi][nj][0], acc[mi][nj][1]);
                        __half2 p1 = __floats2half2_rn(acc[mi][nj][2], acc[mi][nj][3]);
                        if (r0 < NN) *(__half2*)&Ch[(size_t)r0 * 512 + gc] = p0;
                        if (r1 < NN) *(__half2*)&Ch[(size_t)r1 * 512 + gc] = p1;
                    } else if (gc < 576) {
                        int rc = gc - 512;
                        if (r0 < NN) {
                            float2 f = make_float2(acc[mi][nj][0], acc[mi][nj][1]);
                            *(float2*)&Cr[(size_t)r0 * 64 + rc] = f;
                        }
                        if (r1 < NN) {
                            float2 f = make_float2(acc[mi][nj][2], acc[mi][nj][3]);
                            *(float2*)&Cr[(size_t)r1 * 64 + rc] = f;
                        }
                    }
                }
            }
        }
        if (!DYN) return;
    }
}

// ---------------- fp32 tiled GEMM for xb2 with fused fp16/fp32 split store ----------------
__global__ void __launch_bounds__(256)
sgemm_split(const float* __restrict__ A, const float* __restrict__ B, int M, int N, int K) {
    __shared__ float As[128][16];
    __shared__ float Bs[16][64];

    const int m0 = blockIdx.y * 128;
    const int n0 = blockIdx.x * 64;
    const int tid = threadIdx.x;
    const int tx = tid & 15;
    const int ty = tid >> 4;
    const int a_row = tid >> 1;
    const int a_col = (tid & 1) * 8;
    const int b_row = tid >> 4;
    const int b_col = (tid & 15) * 4;

    float acc[8][4];
#pragma unroll
    for (int i = 0; i < 8; i++)
#pragma unroll
        for (int j = 0; j < 4; j++) acc[i][j] = 0.0f;

    for (int k0 = 0; k0 < K; k0 += 16) {
        if (m0 + a_row < M) {
            const float* ap = A + (size_t)(m0 + a_row) * K + k0 + a_col;
            *(float4*)&As[a_row][a_col]     = *(const float4*)(ap);
            *(float4*)&As[a_row][a_col + 4] = *(const float4*)(ap + 4);
        } else {
            float4 z = make_float4(0.f, 0.f, 0.f, 0.f);
            *(float4*)&As[a_row][a_col]     = z;
            *(float4*)&As[a_row][a_col + 4] = z;
        }
        if (n0 + b_col + 3 < N) {
            *(float4*)&Bs[b_row][b_col] =
                *(const float4*)(B + (size_t)(k0 + b_row) * N + n0 + b_col);
        } else {
#pragma unroll
            for (int j = 0; j < 4; j++)
                Bs[b_row][b_col + j] =
                    (n0 + b_col + j < N) ? B[(size_t)(k0 + b_row) * N + n0 + b_col + j] : 0.0f;
        }
        __syncthreads();

#pragma unroll
        for (int kk = 0; kk < 16; kk++) {
            float rB[4];
            *(float4*)rB = *(const float4*)&Bs[kk][tx * 4];
#pragma unroll
            for (int i = 0; i < 8; i++) {
                float a = As[ty * 8 + i][kk];
                acc[i][0] += a * rB[0];
                acc[i][1] += a * rB[1];
                acc[i][2] += a * rB[2];
                acc[i][3] += a * rB[3];
            }
        }
        __syncthreads();
    }

#pragma unroll
    for (int i = 0; i < 8; i++) {
        int m = m0 + ty * 8 + i;
        if (m >= M) continue;
#pragma unroll
        for (int j = 0; j < 4; j++) {
            int n = n0 + tx * 4 + j;
            if (n >= N) continue;
            float v = acc[i][j];
            if (n < 160) g_xb2h[(size_t)m * 160 + n] = __float2half(v);
            else g_root2o[(size_t)m * 20 + (n - 160)] = v;
        }
    }
}

// ---------------- layer-1 aggregation (fp16 gathers, packed rec/w, fused epilogue) ------
__global__ void agg1_kernel(const float* __restrict__ comp, const float* __restrict__ bias) {
    int w = (blockIdx.x * blockDim.x + threadIdx.x) >> 5;
    int lane = threadIdx.x & 31;
    if (w >= NN) return;
    int beg = g_off[w];
    int end = g_off[w + 1];

    float ax = 0.f, ay = 0.f;
    int2 rw = (beg < end) ? g_recw[beg] : make_int2(0, 0);
    for (int i = beg; i < end; i++) {
        int src = rw.x & 0xFFFF;
        int r = rw.x >> 16;
        float inv = __int_as_float(rw.y);
        if (i + 1 < end) rw = g_recw[i + 1];
        float4 c0 = *(const float4*)(comp + r * 8);
        float4 c1 = *(const float4*)(comp + r * 8 + 4);
        const __half2* xr = (const __half2*)(g_xb1h + (size_t)src * 512);
        float mx = 0.f, my = 0.f;
        float2 f;
        f = __half22float2(xr[0 * 32 + lane]); mx += c0.x * f.x; my += c0.x * f.y;
        f = __half22float2(xr[1 * 32 + lane]); mx += c0.y * f.x; my += c0.y * f.y;
        f = __half22float2(xr[2 * 32 + lane]); mx += c0.z * f.x; my += c0.z * f.y;
        f = __half22float2(xr[3 * 32 + lane]); mx += c0.w * f.x; my += c0.w * f.y;
        f = __half22float2(xr[4 * 32 + lane]); mx += c1.x * f.x; my += c1.x * f.y;
        f = __half22float2(xr[5 * 32 + lane]); mx += c1.y * f.x; my += c1.y * f.y;
        f = __half22float2(xr[6 * 32 + lane]); mx += c1.z * f.x; my += c1.z * f.y;
        f = __half22float2(xr[7 * 32 + lane]); mx += c1.w * f.x; my += c1.w * f.y;
        ax += inv * mx;
        ay += inv * my;
    }
    int o = lane * 2;
    float r0 = ax + g_root1[w * 64 + o]     + bias[o];
    float r1 = ay + g_root1[w * 64 + o + 1] + bias[o + 1];
    g_h[w * 64 + o]     = fmaxf(r0, 0.f);
    g_h[w * 64 + o + 1] = fmaxf(r1, 0.f);
}

// ---------------- layer-2 aggregation (fp16 gathers, packed rec/w, fused epilogue) ------
__global__ void agg2_kernel(const float* __restrict__ comp, const float* __restrict__ bias,
                            float* __restrict__ out) {
    int w = (blockIdx.x * blockDim.x + threadIdx.x) >> 5;
    int lane = threadIdx.x & 31;
    if (w >= NN) return;
    int beg = g_off[w];
    int end = g_off[w + 1];
    int l = (lane < 20) ? lane : 0;

    float acc = 0.f;
    int2 rw = (beg < end) ? g_recw[beg] : make_int2(0, 0);
    for (int i = beg; i < end; i++) {
        int src = rw.x & 0xFFFF;
        int r = rw.x >> 16;
        float inv = __int_as_float(rw.y);
        if (i + 1 < end) rw = g_recw[i + 1];
        float4 c0 = *(const float4*)(comp + r * 8);
        float4 c1 = *(const float4*)(comp + r * 8 + 4);
        const __half* xr = g_xb2h + (size_t)src * 160;
        float m = 0.f;
        m += c0.x * __half2float(xr[0 * 20 + l]);
        m += c0.y * __half2float(xr[1 * 20 + l]);
        m += c0.z * __half2float(xr[2 * 20 + l]);
        m += c0.w * __half2float(xr[3 * 20 + l]);
        m += c1.x * __half2float(xr[4 * 20 + l]);
        m += c1.y * __half2float(xr[5 * 20 + l]);
        m += c1.z * __half2float(xr[6 * 20 + l]);
        m += c1.w * __half2float(xr[7 * 20 + l]);
        acc += inv * m;
    }
    if (lane < 20) {
        out[w * 20 + lane] = acc + g_root2o[w * 20 + lane] + bias[lane];
    }
}

// ---------------- launch (two-stream capture fork for edge prep) ----------------
extern "C" void kernel_launch(void* const* d_in, const int* in_sizes, int n_in,
                              void* d_out, int out_size) {
    const float* x_drug = (const float*)d_in[0];
    const float* drug_w = (const float*)d_in[1];
    const int*   ei     = (const int*)d_in[2];
    const float* basis1 = (const float*)d_in[3];
    const float* comp1  = (const float*)d_in[4];
    const float* root1  = (const float*)d_in[5];
    const float* bias1  = (const float*)d_in[6];
    const float* basis2 = (const float*)d_in[7];
    const float* comp2  = (const float*)d_in[8];
    const float* root2  = (const float*)d_in[9];
    const float* bias2  = (const float*)d_in[10];
    float* out = (float*)d_out;

    void *px, *pbwh, *pbwl, *pb1h, *pb1l, *pxb1h, *proot1, *ph, *pb2;
    cudaGetSymbolAddress(&px,     g_x);
    cudaGetSymbolAddress(&pbwh,   g_BtW_hi);
    cudaGetSymbolAddress(&pbwl,   g_BtW_lo);
    cudaGetSymbolAddress(&pb1h,   g_Bt1_hi);
    cudaGetSymbolAddress(&pb1l,   g_Bt1_lo);
    cudaGetSymbolAddress(&pxb1h,  g_xb1h);
    cudaGetSymbolAddress(&proot1, g_root1);
    cudaGetSymbolAddress(&ph,     g_h);
    cudaGetSymbolAddress(&pb2,    g_Bcat2);

    const int SMEM = 3 * STAGE_W * 4;   // 61440 bytes
    cudaFuncSetAttribute(mma_gemm<1, 0, 0>, cudaFuncAttributeMaxDynamicSharedMemorySize, SMEM);
    cudaFuncSetAttribute(mma_gemm<0, 1, 0>, cudaFuncAttributeMaxDynamicSharedMemorySize, SMEM);

    // Host-side stream/event objects, created once (no device memory involved;
    // identical launched work every call).
    static cudaStream_t sB = nullptr;
    static cudaEvent_t evFork = nullptr, evJoin = nullptr;
    if (sB == nullptr) {
        cudaStreamCreateWithFlags(&sB, cudaStreamNonBlocking);
        cudaEventCreateWithFlags(&evFork, cudaEventDisableTiming);
        cudaEventCreateWithFlags(&evJoin, cudaEventDisableTiming);
    }

    // main: fused setup (zero + weight prep)
    setup_all<<<1024, 256>>>(drug_w, basis1, root1, basis2, root2);

    // fork edge-prep chain onto side stream (depends only on setup_all)
    cudaEventRecord(evFork, 0);
    cudaStreamWaitEvent(sB, evFork, 0);
    deg_kernel<<<(NEDGE + 255) / 256, 256, 0, sB>>>(ei);
    scan_kernel<<<1, 1024, 0, sB>>>();
    scatter_kernel<<<(NEDGE + 255) / 256, 256, 0, sB>>>(ei);
    cudaEventRecord(evJoin, sB);

    // main: x = x_drug @ drug_w (overlaps with edge prep)
    mma_gemm<1, 0, 0><<<296, 256, SMEM>>>(
        x_drug, nullptr, nullptr, 2048,
        (const __half*)pbwh, (const __half*)pbwl, 2048,
        128, 16, (float*)px, nullptr, nullptr);

    // main: xb1 = x @ [basis1|root1], A read as fp32 with in-kernel fp16 split (no cvtx pass)
    mma_gemm<0, 1, 0><<<dim3(5, 79), 256, SMEM>>>(
        (const float*)px, nullptr, nullptr, 128,
        (const __half*)pb1h, (const __half*)pb1l, 128,
        576, 8, nullptr, (__half*)pxb1h, (float*)proot1);

    // join: agg1 needs both the GEMM chain and the edge-prep chain
    cudaStreamWaitEvent(0, evJoin, 0);
    agg1_kernel<<<(NN * 32 + 255) / 256, 256>>>(comp1, bias1);

    // main: xb2 = h @ [basis2|root2] with fused split store
    sgemm_split<<<dim3(3, 79), 256>>>((const float*)ph, (const float*)pb2, NN, 180, 64);

    // main: layer-2 aggregation -> out
    agg2_kernel<<<(NN * 32 + 255) / 256, 256>>>(comp2, bias2, out);
}

// round 16
// speedup vs baseline: 1.2130x; 1.0010x over previous
#include <cuda_runtime.h>
#include <cuda_fp16.h>
#include <cstdint>

#define NN 10000
#define RR 100
#define EE 5000
#define NEDGE (RR * EE)

// ---------------- scratch (device globals; no allocations) ----------------
__device__ int   g_deg[RR * NN];
__device__ int   g_cnt[NN];
__device__ int   g_off[NN + 1];
__device__ int   g_cur[NN];
__device__ int2  g_recw[NEDGE];           // packed {(r<<16)|src, 1/deg bits}, grouped by dst
__device__ unsigned int g_ctr;            // dynamic unit counter for gemm1
__device__ float g_x[NN * 128];           // x = x_drug @ drug_w (atomic accumulated)
__device__ __half g_BtW_hi[128 * 2048];   // drug_w^T fp16-hi
__device__ __half g_BtW_lo[128 * 2048];   // drug_w^T fp16-lo
__device__ __half g_Bt1_hi[576 * 128];    // [basis1|root1]^T fp16-hi
__device__ __half g_Bt1_lo[576 * 128];
__device__ __half g_xb1h[NN * 512];       // x @ basis1 (fp16)
__device__ float g_root1[NN * 64];        // x @ root1 (fp32)
__device__ float g_h[NN * 64];            // layer-1 output (post relu)
__device__ float g_Bcat2[64 * 180];       // [basis2 (8x20) | root2 (20)]
__device__ __half g_xb2h[NN * 160];
__device__ float g_root2o[NN * 20];

// GEMM1 unit schedule: 74 mtiles x 8 K-256 units (592 = 2 x 296 balanced waves)
// + 5 tail mtiles x 32 K-64 quarter units (160) for a packed tail.
#define G1_FULL 592
#define G1_TOTAL (G1_FULL + 160)

// ---------------- helpers ----------------
__device__ __forceinline__ uint32_t smem_to_u32(const void* p) {
    uint32_t a;
    asm("{ .reg .u64 t; cvta.to.shared.u64 t, %1; cvt.u32.u64 %0, t; }" : "=r"(a) : "l"(p));
    return a;
}
#define CP_ASYNC16(dst_u32, gptr) \
    asm volatile("cp.async.cg.shared.global [%0], [%1], 16;" :: "r"(dst_u32), "l"(gptr) : "memory")
#define CP_COMMIT() asm volatile("cp.async.commit_group;" ::: "memory")
#define CP_WAIT1()  asm volatile("cp.async.wait_group 1;" ::: "memory")
#define CP_WAIT0()  asm volatile("cp.async.wait_group 0;" ::: "memory")

__device__ __forceinline__ void ldsm4(uint32_t* r, uint32_t addr) {
    asm volatile("ldmatrix.sync.aligned.m8n8.x4.shared.b16 {%0,%1,%2,%3}, [%4];"
        : "=r"(r[0]), "=r"(r[1]), "=r"(r[2]), "=r"(r[3]) : "r"(addr));
}
__device__ __forceinline__ void splitpair(float a, float b, uint32_t& h, uint32_t& l) {
    __half ha = __float2half_rn(a), hb = __float2half_rn(b);
    __half la = __float2half_rn(a - __half2float(ha));
    __half lb = __float2half_rn(b - __half2float(hb));
    __half2 H = __halves2half2(ha, hb), L = __halves2half2(la, lb);
    h = *(uint32_t*)&H;
    l = *(uint32_t*)&L;
}
__device__ __forceinline__ void mma16(float* d, const uint32_t* a, uint32_t b0, uint32_t b1) {
    asm volatile("mma.sync.aligned.m16n8k16.row.col.f32.f16.f16.f32 "
        "{%0,%1,%2,%3}, {%4,%5,%6,%7}, {%8,%9}, {%0,%1,%2,%3};"
        : "+f"(d[0]), "+f"(d[1]), "+f"(d[2]), "+f"(d[3])
        : "r"(a[0]), "r"(a[1]), "r"(a[2]), "r"(a[3]), "r"(b0), "r"(b1));
}

// ---------------- main-chain setup: zero g_x/ctr + GEMM weight prep ----------------
__global__ void setup_main(const float* __restrict__ w,
                           const float* __restrict__ basis1, const float* __restrict__ root1) {
    int stride = gridDim.x * blockDim.x;
    int i0 = blockIdx.x * blockDim.x + threadIdx.x;
    for (int i = i0; i < NN * 128; i += stride) g_x[i] = 0.0f;
    if (i0 == 0) g_ctr = 0u;
    for (int idx = i0; idx < 2048 * 128; idx += stride) {
        int k = idx >> 7, n = idx & 127;
        float v = w[idx];
        __half h = __float2half_rn(v);
        g_BtW_hi[n * 2048 + k] = h;
        g_BtW_lo[n * 2048 + k] = __float2half_rn(v - __half2float(h));
    }
    for (int idx = i0; idx < 576 * 128; idx += stride) {
        int c = idx >> 7, i = idx & 127;
        float v = (c < 512) ? basis1[(c >> 6) * 128 * 64 + i * 64 + (c & 63)]
                            : root1[i * 64 + (c - 512)];
        __half h = __float2half_rn(v);
        g_Bt1_hi[c * 128 + i] = h;
        g_Bt1_lo[c * 128 + i] = __float2half_rn(v - __half2float(h));
    }
}

// ---------------- side-chain setup: zero deg/cnt + layer-2 weights ----------------
__global__ void setup_side(const float* __restrict__ basis2, const float* __restrict__ root2) {
    int stride = gridDim.x * blockDim.x;
    int i0 = blockIdx.x * blockDim.x + threadIdx.x;
    for (int i = i0; i < RR * NN; i += stride) g_deg[i] = 0;
    for (int i = i0; i < NN; i += stride) g_cnt[i] = 0;
    for (int idx = i0; idx < 64 * 180; idx += stride) {
        int i = idx / 180;
        int c = idx - i * 180;
        g_Bcat2[idx] = (c < 160) ? basis2[(c / 20) * 64 * 20 + i * 20 + (c % 20)]
                                 : root2[i * 20 + (c - 160)];
    }
}

// ---------------- degree + per-dst count (side stream) ----------------
__global__ void deg_kernel(const int* __restrict__ ei) {
    int idx = blockIdx.x * blockDim.x + threadIdx.x;
    if (idx >= NEDGE) return;
    int r = idx / EE;
    int e = idx - r * EE;
    int dst = ei[r * 2 * EE + EE + e];
    atomicAdd(&g_deg[r * NN + dst], 1);
    atomicAdd(&g_cnt[dst], 1);
}

// ---------------- single-block exclusive scan ----------------
__global__ void scan_kernel() {
    __shared__ int sp[1024];
    int t = threadIdx.x;
    int base = t * 10;
    int loc[10];
    int s = 0;
#pragma unroll
    for (int j = 0; j < 10; j++) {
        int idx = base + j;
        int v = (idx < NN) ? g_cnt[idx] : 0;
        loc[j] = s;
        s += v;
    }
    sp[t] = s;
    __syncthreads();
    for (int off = 1; off < 1024; off <<= 1) {
        int v = (t >= off) ? sp[t - off] : 0;
        __syncthreads();
        sp[t] += v;
        __syncthreads();
    }
    int pre = (t > 0) ? sp[t - 1] : 0;
#pragma unroll
    for (int j = 0; j < 10; j++) {
        int idx = base + j;
        if (idx < NN) {
            int o = pre + loc[j];
            g_off[idx] = o;
            g_cur[idx] = o;
        }
    }
    if (t == 0) g_off[NN] = NEDGE;
}

// ---------------- scatter edges into dst buckets (packed rec + 1/deg) ----------------
__global__ void scatter_kernel(const int* __restrict__ ei) {
    int idx = blockIdx.x * blockDim.x + threadIdx.x;
    if (idx >= NEDGE) return;
    int r = idx / EE;
    int e = idx - r * EE;
    const int* eir = ei + r * 2 * EE;
    int src = eir[e];
    int dst = eir[EE + e];
    int pos = atomicAdd(&g_cur[dst], 1);
    float w = 1.0f / (float)max(g_deg[r * NN + dst], 1);
    g_recw[pos] = make_int2((r << 16) | src, __float_as_int(w));
}

// ================= pipelined mma.sync fp16-split GEMM (3-product, ldmatrix) =================
#define LP2 20
#define STAGE_W (2 * 128 * LP2)

template<int DYN, int EPI, int AH>
__global__ void __launch_bounds__(256, 2)
mma_gemm(const float* __restrict__ Af,
         const __half* __restrict__ Ahg, const __half* __restrict__ Alg, int lda,
         const __half* __restrict__ Bth, const __half* __restrict__ Btl, int ldb,
         int Ntot, int nchunks,
         float* __restrict__ Cf, __half* __restrict__ Ch, float* __restrict__ Cr) {
    extern __shared__ uint32_t sm[];
    const uint32_t sbase = smem_to_u32(sm);
    __shared__ int s_u;

    const int tid = threadIdx.x;
    const int wid = tid >> 5;
    const int lane = tid & 31;
    const int g = lane >> 2;
    const int tig = lane & 3;
    const int m_warp = (wid & 3) * 32;
    const int n_warp = (wid >> 2) * 64;
    const int lrow = tid >> 1;        // 0..127
    const int part = tid & 1;         // 8-element half-row

    // ---- per-lane ldmatrix base offsets ----
    const int lrow8 = lane & 7;
    const int aRow = m_warp + ((lane >> 3) & 1) * 8 + lrow8;       // + mi*16
    const int aK = (lane >> 4) * 4;
    const uint32_t aOff0 = (uint32_t)((aRow)      * LP2 + aK) * 4; // mi=0 (bytes)
    const uint32_t aOff1 = (uint32_t)((aRow + 16) * LP2 + aK) * 4; // mi=1
    const int bCol = n_warp + (lane >> 4) * 8 + lrow8;             // + p*16
    const int bK = ((lane >> 3) & 1) * 4;
    const uint32_t bOffBase = (uint32_t)((128 + bCol) * LP2 + bK) * 4;

    float4 rAv[2][2];                 // A register prefetch slots (AH=0)

    while (true) {
        int m0, n0, kbeg0, nch;
        if (DYN) {
            __syncthreads();                 // prior unit's compute done; smem reusable
            if (tid == 0) s_u = (int)atomicAdd(&g_ctr, 1u);
            __syncthreads();
            int u = s_u;
            if (u >= G1_TOTAL) return;
            if (u < G1_FULL) {               // balanced waves: 74 mtiles x 8 K-256 slices
                m0 = (u % 74) * 128;
                kbeg0 = (u / 74) * 256;
                nch = 16;
            } else {                         // packed tail: 5 mtiles x 32 K-64 slices
                int v = u - G1_FULL;
                m0 = (74 + (v % 5)) * 128;
                kbeg0 = (v / 5) * 64;
                nch = 4;
            }
            n0 = 0;
        } else {
            m0 = blockIdx.y * 128;
            n0 = blockIdx.x * 128;
            kbeg0 = 0;
            nch = nchunks;
        }

        const int gm = m0 + lrow;
        const int gn = n0 + lrow;
        const bool mok = (gm < NN);
        const bool nok = (gn < Ntot);

        // ---- issue helpers ----
        auto issueA = [&](int ch, int slot, int st) {
            int kbeg = kbeg0 + ch * 16;
            if (AH == 0) {
                if (mok) {
                    const float* ap = Af + (size_t)gm * lda + kbeg + part * 8;
                    rAv[slot][0] = *(const float4*)ap;
                    rAv[slot][1] = *(const float4*)(ap + 4);
                } else {
                    rAv[slot][0] = make_float4(0.f, 0.f, 0.f, 0.f);
                    rAv[slot][1] = make_float4(0.f, 0.f, 0.f, 0.f);
                }
            } else {
                if (mok) {
                    uint32_t d = sbase + (uint32_t)(st * STAGE_W + lrow * LP2 + part * 4) * 4;
                    CP_ASYNC16(d,      Ahg + (size_t)gm * lda + kbeg + part * 8);
                    CP_ASYNC16(d + 32, Alg + (size_t)gm * lda + kbeg + part * 8);
                }
            }
        };
        auto stsA = [&](int slot, int st) {   // AH=0 only
            uint4 H, L;
            splitpair(rAv[slot][0].x, rAv[slot][0].y, H.x, L.x);
            splitpair(rAv[slot][0].z, rAv[slot][0].w, H.y, L.y);
            splitpair(rAv[slot][1].x, rAv[slot][1].y, H.z, L.z);
            splitpair(rAv[slot][1].z, rAv[slot][1].w, H.w, L.w);
            uint32_t* p = sm + st * STAGE_W + lrow * LP2 + part * 4;
            *(uint4*)p = H;
            *(uint4*)(p + 8) = L;
        };
        auto issueB = [&](int ch, int st) {
            if (nok) {
                int kbeg = kbeg0 + ch * 16;
                uint32_t d = sbase + (uint32_t)(st * STAGE_W + 128 * LP2 + lrow * LP2 + part * 4) * 4;
                CP_ASYNC16(d,      Bth + (size_t)gn * ldb + kbeg + part * 8);
                CP_ASYNC16(d + 32, Btl + (size_t)gn * ldb + kbeg + part * 8);
            }
        };

        float acc[2][8][4];
#pragma unroll
        for (int i = 0; i < 2; i++)
#pragma unroll
            for (int j = 0; j < 8; j++)
#pragma unroll
                for (int q = 0; q < 4; q++) acc[i][j][q] = 0.f;

        // ---- prologue: chunks 0 and 1 in flight ----
        issueA(0, 0, 0); issueB(0, 0); CP_COMMIT();
        issueA(1, 1, 1); issueB(1, 1); CP_COMMIT();
        if (AH == 0) stsA(0, 0);

        // ---- main pipeline ----
        for (int ch = 0; ch < nch; ch++) {
            if (ch + 1 < nch) { CP_WAIT1(); } else { CP_WAIT0(); }
            __syncthreads();

            if (AH == 0 && ch + 1 < nch) stsA((ch + 1) & 1, (ch + 1) % 3);
            if (ch + 2 < nch) {
                issueA(ch + 2, ch & 1, (ch + 2) % 3);
                issueB(ch + 2, (ch + 2) % 3);
                CP_COMMIT();
            }

            // ---- compute chunk ch on stage ch%3 (ldmatrix fragments) ----
            const uint32_t stb = sbase + (uint32_t)((ch % 3) * STAGE_W) * 4;
            uint32_t ah[2][4], al[2][4];
            ldsm4(ah[0], stb + aOff0);
            ldsm4(ah[1], stb + aOff1);
            ldsm4(al[0], stb + aOff0 + 32);
            ldsm4(al[1], stb + aOff1 + 32);
#pragma unroll
            for (int p = 0; p < 4; p++) {
                uint32_t bAddr = stb + bOffBase + (uint32_t)(p * 16 * LP2) * 4;
                uint32_t bh[4], bl[4];
                ldsm4(bh, bAddr);
                ldsm4(bl, bAddr + 32);
                const int nj0 = 2 * p, nj1 = 2 * p + 1;
                mma16(acc[0][nj0], ah[0], bh[0], bh[1]);
                mma16(acc[1][nj0], ah[1], bh[0], bh[1]);
                mma16(acc[0][nj1], ah[0], bh[2], bh[3]);
                mma16(acc[1][nj1], ah[1], bh[2], bh[3]);
                mma16(acc[0][nj0], al[0], bh[0], bh[1]);
                mma16(acc[1][nj0], al[1], bh[0], bh[1]);
                mma16(acc[0][nj1], al[0], bh[2], bh[3]);
                mma16(acc[1][nj1], al[1], bh[2], bh[3]);
                mma16(acc[0][nj0], ah[0], bl[0], bl[1]);
                mma16(acc[1][nj0], ah[1], bl[0], bl[1]);
                mma16(acc[0][nj1], ah[0], bl[2], bl[3]);
                mma16(acc[1][nj1], ah[1], bl[2], bl[3]);
            }
        }

        // ---- epilogue ----
#pragma unroll
        for (int mi = 0; mi < 2; mi++) {
            int r0 = m0 + m_warp + mi * 16 + g;
            int r1 = r0 + 8;
#pragma unroll
            for (int nj = 0; nj < 8; nj++) {
                int gc = n0 + n_warp + nj * 8 + tig * 2;
                if (EPI == 0) {
                    if (r0 < NN) {
                        atomicAdd(&Cf[(size_t)r0 * 128 + gc],     acc[mi][nj][0]);
                        atomicAdd(&Cf[(size_t)r0 * 128 + gc + 1], acc[mi][nj][1]);
                    }
                    if (r1 < NN) {
                        atomicAdd(&Cf[(size_t)r1 * 128 + gc],     acc[mi][nj][2]);
                        atomicAdd(&Cf[(size_t)r1 * 128 + gc + 1], acc[mi][nj][3]);
                    }
                } else {
                    if (gc < 512) {
                        __half2 p0 = __floats2half2_rn(acc[mi][nj][0], acc[mi][nj][1]);
                        __half2 p1 = __floats2half2_rn(acc[mi][nj][2], acc[mi][nj][3]);
                        if (r0 < NN) *(__half2*)&Ch[(size_t)r0 * 512 + gc] = p0;
                        if (r1 < NN) *(__half2*)&Ch[(size_t)r1 * 512 + gc] = p1;
                    } else if (gc < 576) {
                        int rc = gc - 512;
                        if (r0 < NN) {
                            float2 f = make_float2(acc[mi][nj][0], acc[mi][nj][1]);
                            *(float2*)&Cr[(size_t)r0 * 64 + rc] = f;
                        }
                        if (r1 < NN) {
                            float2 f = make_float2(acc[mi][nj][2], acc[mi][nj][3]);
                            *(float2*)&Cr[(size_t)r1 * 64 + rc] = f;
                        }
                    }
                }
            }
        }
        if (!DYN) return;
    }
}

// ---------------- fp32 tiled GEMM for xb2 with fused fp16/fp32 split store ----------------
__global__ void __launch_bounds__(256)
sgemm_split(const float* __restrict__ A, const float* __restrict__ B, int M, int N, int K) {
    __shared__ float As[128][16];
    __shared__ float Bs[16][64];

    const int m0 = blockIdx.y * 128;
    const int n0 = blockIdx.x * 64;
    const int tid = threadIdx.x;
    const int tx = tid & 15;
    const int ty = tid >> 4;
    const int a_row = tid >> 1;
    const int a_col = (tid & 1) * 8;
    const int b_row = tid >> 4;
    const int b_col = (tid & 15) * 4;

    float acc[8][4];
#pragma unroll
    for (int i = 0; i < 8; i++)
#pragma unroll
        for (int j = 0; j < 4; j++) acc[i][j] = 0.0f;

    for (int k0 = 0; k0 < K; k0 += 16) {
        if (m0 + a_row < M) {
            const float* ap = A + (size_t)(m0 + a_row) * K + k0 + a_col;
            *(float4*)&As[a_row][a_col]     = *(const float4*)(ap);
            *(float4*)&As[a_row][a_col + 4] = *(const float4*)(ap + 4);
        } else {
            float4 z = make_float4(0.f, 0.f, 0.f, 0.f);
            *(float4*)&As[a_row][a_col]     = z;
            *(float4*)&As[a_row][a_col + 4] = z;
        }
        if (n0 + b_col + 3 < N) {
            *(float4*)&Bs[b_row][b_col] =
                *(const float4*)(B + (size_t)(k0 + b_row) * N + n0 + b_col);
        } else {
#pragma unroll
            for (int j = 0; j < 4; j++)
                Bs[b_row][b_col + j] =
                    (n0 + b_col + j < N) ? B[(size_t)(k0 + b_row) * N + n0 + b_col + j] : 0.0f;
        }
        __syncthreads();

#pragma unroll
        for (int kk = 0; kk < 16; kk++) {
            float rB[4];
            *(float4*)rB = *(const float4*)&Bs[kk][tx * 4];
#pragma unroll
            for (int i = 0; i < 8; i++) {
                float a = As[ty * 8 + i][kk];
                acc[i][0] += a * rB[0];
                acc[i][1] += a * rB[1];
                acc[i][2] += a * rB[2];
                acc[i][3] += a * rB[3];
            }
        }
        __syncthreads();
    }

#pragma unroll
    for (int i = 0; i < 8; i++) {
        int m = m0 + ty * 8 + i;
        if (m >= M) continue;
#pragma unroll
        for (int j = 0; j < 4; j++) {
            int n = n0 + tx * 4 + j;
            if (n >= N) continue;
            float v = acc[i][j];
            if (n < 160) g_xb2h[(size_t)m * 160 + n] = __float2half(v);
            else g_root2o[(size_t)m * 20 + (n - 160)] = v;
        }
    }
}

// ---------------- layer-1 aggregation (fp16 gathers, packed rec/w, fused epilogue) ------
__global__ void agg1_kernel(const float* __restrict__ comp, const float* __restrict__ bias) {
    int w = (blockIdx.x * blockDim.x + threadIdx.x) >> 5;
    int lane = threadIdx.x & 31;
    if (w >= NN) return;
    int beg = g_off[w];
    int end = g_off[w + 1];

    float ax = 0.f, ay = 0.f;
    int2 rw = (beg < end) ? g_recw[beg] : make_int2(0, 0);
    for (int i = beg; i < end; i++) {
        int src = rw.x & 0xFFFF;
        int r = rw.x >> 16;
        float inv = __int_as_float(rw.y);
        if (i + 1 < end) rw = g_recw[i + 1];
        float4 c0 = *(const float4*)(comp + r * 8);
        float4 c1 = *(const float4*)(comp + r * 8 + 4);
        const __half2* xr = (const __half2*)(g_xb1h + (size_t)src * 512);
        float mx = 0.f, my = 0.f;
        float2 f;
        f = __half22float2(xr[0 * 32 + lane]); mx += c0.x * f.x; my += c0.x * f.y;
        f = __half22float2(xr[1 * 32 + lane]); mx += c0.y * f.x; my += c0.y * f.y;
        f = __half22float2(xr[2 * 32 + lane]); mx += c0.z * f.x; my += c0.z * f.y;
        f = __half22float2(xr[3 * 32 + lane]); mx += c0.w * f.x; my += c0.w * f.y;
        f = __half22float2(xr[4 * 32 + lane]); mx += c1.x * f.x; my += c1.x * f.y;
        f = __half22float2(xr[5 * 32 + lane]); mx += c1.y * f.x; my += c1.y * f.y;
        f = __half22float2(xr[6 * 32 + lane]); mx += c1.z * f.x; my += c1.z * f.y;
        f = __half22float2(xr[7 * 32 + lane]); mx += c1.w * f.x; my += c1.w * f.y;
        ax += inv * mx;
        ay += inv * my;
    }
    int o = lane * 2;
    float r0 = ax + g_root1[w * 64 + o]     + bias[o];
    float r1 = ay + g_root1[w * 64 + o + 1] + bias[o + 1];
    g_h[w * 64 + o]     = fmaxf(r0, 0.f);
    g_h[w * 64 + o + 1] = fmaxf(r1, 0.f);
}

// ---------------- layer-2 aggregation (fp16 gathers, packed rec/w, fused epilogue) ------
__global__ void agg2_kernel(const float* __restrict__ comp, const float* __restrict__ bias,
                            float* __restrict__ out) {
    int w = (blockIdx.x * blockDim.x + threadIdx.x) >> 5;
    int lane = threadIdx.x & 31;
    if (w >= NN) return;
    int beg = g_off[w];
    int end = g_off[w + 1];
    int l = (lane < 20) ? lane : 0;

    float acc = 0.f;
    int2 rw = (beg < end) ? g_recw[beg] : make_int2(0, 0);
    for (int i = beg; i < end; i++) {
        int src = rw.x & 0xFFFF;
        int r = rw.x >> 16;
        float inv = __int_as_float(rw.y);
        if (i + 1 < end) rw = g_recw[i + 1];
        float4 c0 = *(const float4*)(comp + r * 8);
        float4 c1 = *(const float4*)(comp + r * 8 + 4);
        const __half* xr = g_xb2h + (size_t)src * 160;
        float m = 0.f;
        m += c0.x * __half2float(xr[0 * 20 + l]);
        m += c0.y * __half2float(xr[1 * 20 + l]);
        m += c0.z * __half2float(xr[2 * 20 + l]);
        m += c0.w * __half2float(xr[3 * 20 + l]);
        m += c1.x * __half2float(xr[4 * 20 + l]);
        m += c1.y * __half2float(xr[5 * 20 + l]);
        m += c1.z * __half2float(xr[6 * 20 + l]);
        m += c1.w * __half2float(xr[7 * 20 + l]);
        acc += inv * m;
    }
    if (lane < 20) {
        out[w * 20 + lane] = acc + g_root2o[w * 20 + lane] + bias[lane];
    }
}

// ---------------- launch (two-stream capture fork for edge prep + side setup) ----------------
extern "C" void kernel_launch(void* const* d_in, const int* in_sizes, int n_in,
                              void* d_out, int out_size) {
    const float* x_drug = (const float*)d_in[0];
    const float* drug_w = (const float*)d_in[1];
    const int*   ei     = (const int*)d_in[2];
    const float* basis1 = (const float*)d_in[3];
    const float* comp1  = (const float*)d_in[4];
    const float* root1  = (const float*)d_in[5];
    const float* bias1  = (const float*)d_in[6];
    const float* basis2 = (const float*)d_in[7];
    const float* comp2  = (const float*)d_in[8];
    const float* root2  = (const float*)d_in[9];
    const float* bias2  = (const float*)d_in[10];
    float* out = (float*)d_out;

    void *px, *pbwh, *pbwl, *pb1h, *pb1l, *pxb1h, *proot1, *ph, *pb2;
    cudaGetSymbolAddress(&px,     g_x);
    cudaGetSymbolAddress(&pbwh,   g_BtW_hi);
    cudaGetSymbolAddress(&pbwl,   g_BtW_lo);
    cudaGetSymbolAddress(&pb1h,   g_Bt1_hi);
    cudaGetSymbolAddress(&pb1l,   g_Bt1_lo);
    cudaGetSymbolAddress(&pxb1h,  g_xb1h);
    cudaGetSymbolAddress(&proot1, g_root1);
    cudaGetSymbolAddress(&ph,     g_h);
    cudaGetSymbolAddress(&pb2,    g_Bcat2);

    const int SMEM = 3 * STAGE_W * 4;   // 61440 bytes
    cudaFuncSetAttribute(mma_gemm<1, 0, 0>, cudaFuncAttributeMaxDynamicSharedMemorySize, SMEM);
    cudaFuncSetAttribute(mma_gemm<0, 1, 0>, cudaFuncAttributeMaxDynamicSharedMemorySize, SMEM);

    // Host-side stream/event objects, created once (no device memory involved;
    // identical launched work every call).
    static cudaStream_t sB = nullptr;
    static cudaEvent_t evFork = nullptr, evJoin = nullptr;
    if (sB == nullptr) {
        cudaStreamCreateWithFlags(&sB, cudaStreamNonBlocking);
        cudaEventCreateWithFlags(&evFork, cudaEventDisableTiming);
        cudaEventCreateWithFlags(&evJoin, cudaEventDisableTiming);
    }

    // fork side chain at capture start: side setup + edge prep fully parallel
    cudaEventRecord(evFork, 0);
    cudaStreamWaitEvent(sB, evFork, 0);
    setup_side<<<1024, 256, 0, sB>>>(basis2, root2);
    deg_kernel<<<(NEDGE + 255) / 256, 256, 0, sB>>>(ei);
    scan_kernel<<<1, 1024, 0, sB>>>();
    scatter_kernel<<<(NEDGE + 255) / 256, 256, 0, sB>>>(ei);
    cudaEventRecord(evJoin, sB);

    // main: GEMM-chain setup
    setup_main<<<1024, 256>>>(drug_w, basis1, root1);

    // main: x = x_drug @ drug_w (balanced waves + packed tail)
    mma_gemm<1, 0, 0><<<296, 256, SMEM>>>(
        x_drug, nullptr, nullptr, 2048,
        (const __half*)pbwh, (const __half*)pbwl, 2048,
        128, 16, (float*)px, nullptr, nullptr);

    // main: xb1 = x @ [basis1|root1], A read as fp32 with in-kernel fp16 split
    mma_gemm<0, 1, 0><<<dim3(5, 79), 256, SMEM>>>(
        (const float*)px, nullptr, nullptr, 128,
        (const __half*)pb1h, (const __half*)pb1l, 128,
        576, 8, nullptr, (__half*)pxb1h, (float*)proot1);

    // join: agg1 needs both the GEMM chain and the edge-prep chain
    cudaStreamWaitEvent(0, evJoin, 0);
    agg1_kernel<<<(NN * 32 + 255) / 256, 256>>>(comp1, bias1);

    // main: xb2 = h @ [basis2|root2] with fused split store
    sgemm_split<<<dim3(3, 79), 256>>>((const float*)ph, (const float*)pb2, NN, 180, 64);

    // main: layer-2 aggregation -> out
    agg2_kernel<<<(NN * 32 + 255) / 256, 256>>>(comp2, bias2, out);
}